// round 7
// baseline (speedup 1.0000x reference)
#include <cuda_runtime.h>
#include <math.h>

// ---------------- Problem dims (compile-time) ----------------
#define B_      2
#define S_      2048
#define T_      4096          // B*S tokens
#define D_      1024          // model dim
#define H_      16
#define DH_     64
#define DM_     4096
#define EPSV    1e-5f
#define IGNOREV -100000.0f

// ---------------- Scratch (static device globals; no allocation) ----------------
__device__ float g_xn  [T_ * D_];
__device__ float g_q   [T_ * D_];
__device__ float g_k   [T_ * D_];
__device__ float g_v   [T_ * D_];
__device__ float g_z   [T_ * D_];
__device__ float g_rmid[T_ * D_];
__device__ float g_mln [T_ * D_];
__device__ float g_hid [(size_t)T_ * DM_];
__device__ float g_WqT [D_ * D_];
__device__ float g_WkT [D_ * D_];
__device__ float g_WvT [D_ * D_];
__device__ float g_WoT [D_ * D_];
__device__ float g_WinT [(size_t)D_ * DM_];   // [K=1024][N=4096]
__device__ float g_WoutT[(size_t)DM_ * D_];   // [K=4096][N=1024]

// ---------------- LayerNorm (no affine): y = (x - mean) * rsqrt(var + eps) ----------------
__global__ void ln_kernel(const float* __restrict__ src, float* __restrict__ dst) {
    int row = blockIdx.x;
    const float4* x4 = (const float4*)(src + (size_t)row * D_);
    float4 vv = x4[threadIdx.x];                         // 256 threads * 4 = 1024
    float s  = vv.x + vv.y + vv.z + vv.w;
    float s2 = vv.x*vv.x + vv.y*vv.y + vv.z*vv.z + vv.w*vv.w;
    #pragma unroll
    for (int o = 16; o > 0; o >>= 1) {
        s  += __shfl_xor_sync(0xffffffffu, s,  o);
        s2 += __shfl_xor_sync(0xffffffffu, s2, o);
    }
    __shared__ float ws[8], ws2[8];
    __shared__ float s_mean, s_r;
    int w = threadIdx.x >> 5;
    if ((threadIdx.x & 31) == 0) { ws[w] = s; ws2[w] = s2; }
    __syncthreads();
    if (threadIdx.x == 0) {
        float a = 0.f, b2 = 0.f;
        #pragma unroll
        for (int i = 0; i < 8; i++) { a += ws[i]; b2 += ws2[i]; }
        float mean = a * (1.f / D_);
        float var  = b2 * (1.f / D_) - mean * mean;
        s_mean = mean;
        s_r    = rsqrtf(var + EPSV);
    }
    __syncthreads();
    float mean = s_mean, r = s_r;
    float4 o;
    o.x = (vv.x - mean) * r; o.y = (vv.y - mean) * r;
    o.z = (vv.z - mean) * r; o.w = (vv.w - mean) * r;
    ((float4*)(dst + (size_t)row * D_))[threadIdx.x] = o;
}

// ---------------- Tiled transpose: in [N,K] row-major -> out [K,N] row-major ----------------
__global__ void transpose_kernel(const float* __restrict__ in, float* __restrict__ out,
                                 int N, int K) {
    __shared__ float tile[32][33];
    int k0 = blockIdx.x * 32, n0 = blockIdx.y * 32;
    int tx = threadIdx.x, ty = threadIdx.y;
    tile[ty][tx] = in[(size_t)(n0 + ty) * K + (k0 + tx)];
    __syncthreads();
    out[(size_t)(k0 + ty) * N + (n0 + tx)] = tile[tx][ty];
}

// W_O is [H, D, DH]; build WoT[k = h*64+dh][d] = W_O[h][d][dh]  (writes coalesced)
__global__ void transpose_wo_kernel(const float* __restrict__ wo, float* __restrict__ out) {
    int idx = blockIdx.x * 256 + threadIdx.x;   // 1M elements
    int d  = idx & (D_ - 1);
    int kk = idx >> 10;
    int h  = kk >> 6;
    int dh = kk & 63;
    out[idx] = wo[(size_t)h * D_ * DH_ + (size_t)d * DH_ + dh];
}

// ---------------- GELU (gpt2 "new") ----------------
__device__ __forceinline__ float gelu_new_f(float x) {
    float x3 = x * x * x;
    return 0.5f * x * (1.0f + tanhf(0.7978845608028654f * (x + 0.044715f * x3)));
}

// ---------------- SGEMM: C[M,N] = epilogue(A[M,K] @ Bt[K,N] + bias[N]) ----------------
// ACT: 0=none, 1=gelu_new.  RES: 0=none, 1=add resid[M,N].
template <int ACT, int RES>
__global__ void __launch_bounds__(256)
sgemm_kernel(int M, int N, int K,
             const float* __restrict__ A, const float* __restrict__ Bt,
             const float* __restrict__ bias, const float* __restrict__ resid,
             float* __restrict__ C) {
    constexpr int BM = 128, BN = 128, BK = 8, TM = 8, TN = 8;
    __shared__ float As[BK * BM];   // transposed: As[k][m]
    __shared__ float Bs[BK * BN];   // Bs[k][n]

    int tid  = threadIdx.x;
    int brow = blockIdx.y, bcol = blockIdx.x;
    const float* Ap = A  + (size_t)brow * BM * K;
    const float* Bp = Bt + (size_t)bcol * BN;

    int aRow = tid >> 1, aCol = (tid & 1) * 4;     // 128x8 tile, float4 per thread
    int bRow = tid >> 5, bCol = (tid & 31) * 4;    // 8x128 tile, float4 per thread
    int tr = tid >> 4, tc = tid & 15;              // 16x16 thread grid -> 8x8 micro-tile

    float acc[TM][TN];
    #pragma unroll
    for (int i = 0; i < TM; i++)
        #pragma unroll
        for (int j = 0; j < TN; j++) acc[i][j] = 0.f;

    for (int kb = 0; kb < K; kb += BK) {
        float4 a4 = *(const float4*)(Ap + (size_t)aRow * K + kb + aCol);
        As[(aCol + 0) * BM + aRow] = a4.x;
        As[(aCol + 1) * BM + aRow] = a4.y;
        As[(aCol + 2) * BM + aRow] = a4.z;
        As[(aCol + 3) * BM + aRow] = a4.w;
        *(float4*)(Bs + bRow * BN + bCol) =
            *(const float4*)(Bp + (size_t)(kb + bRow) * N + bCol);
        __syncthreads();

        #pragma unroll
        for (int kk = 0; kk < BK; kk++) {
            float4 a0 = *(const float4*)(As + kk * BM + tr * TM);
            float4 a1 = *(const float4*)(As + kk * BM + tr * TM + 4);
            float4 b0 = *(const float4*)(Bs + kk * BN + tc * TN);
            float4 b1 = *(const float4*)(Bs + kk * BN + tc * TN + 4);
            float rm[TM] = {a0.x, a0.y, a0.z, a0.w, a1.x, a1.y, a1.z, a1.w};
            float rn[TN] = {b0.x, b0.y, b0.z, b0.w, b1.x, b1.y, b1.z, b1.w};
            #pragma unroll
            for (int i = 0; i < TM; i++)
                #pragma unroll
                for (int j = 0; j < TN; j++)
                    acc[i][j] += rm[i] * rn[j];
        }
        __syncthreads();
    }

    int row0 = brow * BM + tr * TM;
    int col0 = bcol * BN + tc * TN;
    #pragma unroll
    for (int i = 0; i < TM; i++) {
        size_t rbase = (size_t)(row0 + i) * N;
        #pragma unroll
        for (int j = 0; j < TN; j++) {
            int cc = col0 + j;
            float vv = acc[i][j] + bias[cc];
            if (ACT == 1) vv = gelu_new_f(vv);
            if (RES == 1) vv += resid[rbase + cc];
            C[rbase + cc] = vv;
        }
    }
}

// ---------------- Causal flash attention, DH=64, fp32 ----------------
// grid.x = S/64 q-tiles, grid.y = B*H. 256 threads as 16x16; 4x4 micro-tiles.
__global__ void __launch_bounds__(256)
attn_kernel(const float* __restrict__ q, const float* __restrict__ k,
            const float* __restrict__ v, float* __restrict__ z) {
    extern __shared__ float sm[];
    float* Qs = sm;                 // [64][65]
    float* Ks = Qs + 64 * 65;       // [64][65]
    float* Vs = Ks + 64 * 65;       // [64][65]
    float* Ps = Vs + 64 * 65;       // [64][65]

    int qt = blockIdx.x;
    int bh = blockIdx.y;
    int b = bh >> 4, h = bh & 15;
    int tid = threadIdx.x;
    int ty = tid >> 4, tx = tid & 15;
    int r0 = ty * 4, c0 = tx * 4;

    size_t base = (size_t)b * S_ * D_ + (size_t)h * DH_;   // + s*1024 + dh

    // Load Q tile (coalesced float4)
    for (int i = tid; i < 64 * 16; i += 256) {
        int row = i >> 4, c4 = (i & 15) * 4;
        float4 t = *(const float4*)(q + base + (size_t)(qt * 64 + row) * D_ + c4);
        float* dst = Qs + row * 65 + c4;
        dst[0] = t.x; dst[1] = t.y; dst[2] = t.z; dst[3] = t.w;
    }

    float mi[4], li[4], acc[4][4];
    #pragma unroll
    for (int i = 0; i < 4; i++) {
        mi[i] = -1e30f; li[i] = 0.f;
        #pragma unroll
        for (int j = 0; j < 4; j++) acc[i][j] = 0.f;
    }

    for (int jt = 0; jt <= qt; jt++) {
        // Load K and V tiles
        for (int i = tid; i < 64 * 16; i += 256) {
            int row = i >> 4, c4 = (i & 15) * 4;
            size_t goff = base + (size_t)(jt * 64 + row) * D_ + c4;
            float4 tk = *(const float4*)(k + goff);
            float4 tv = *(const float4*)(v + goff);
            float* dk = Ks + row * 65 + c4;
            float* dv = Vs + row * 65 + c4;
            dk[0] = tk.x; dk[1] = tk.y; dk[2] = tk.z; dk[3] = tk.w;
            dv[0] = tv.x; dv[1] = tv.y; dv[2] = tv.z; dv[3] = tv.w;
        }
        __syncthreads();

        // S = Q * K^T (thread computes rows r0..r0+3, key-cols c0..c0+3)
        float s[4][4];
        #pragma unroll
        for (int i = 0; i < 4; i++)
            #pragma unroll
            for (int j = 0; j < 4; j++) s[i][j] = 0.f;

        #pragma unroll 8
        for (int kk = 0; kk < 64; kk++) {
            float aq[4], bk[4];
            #pragma unroll
            for (int i = 0; i < 4; i++) aq[i] = Qs[(r0 + i) * 65 + kk];
            #pragma unroll
            for (int j = 0; j < 4; j++) bk[j] = Ks[(c0 + j) * 65 + kk];
            #pragma unroll
            for (int i = 0; i < 4; i++)
                #pragma unroll
                for (int j = 0; j < 4; j++) s[i][j] += aq[i] * bk[j];
        }

        // Scale then causal mask (diagonal tile only), matching reference order
        #pragma unroll
        for (int i = 0; i < 4; i++)
            #pragma unroll
            for (int j = 0; j < 4; j++) {
                s[i][j] *= 0.125f;   // 1/sqrt(64)
                if (jt == qt && (c0 + j) > (r0 + i)) s[i][j] = IGNOREV;
            }

        // Online softmax per row (reduce over the 16 tx-threads = one half-warp)
        #pragma unroll
        for (int i = 0; i < 4; i++) {
            float mx = fmaxf(fmaxf(s[i][0], s[i][1]), fmaxf(s[i][2], s[i][3]));
            #pragma unroll
            for (int o = 1; o < 16; o <<= 1)
                mx = fmaxf(mx, __shfl_xor_sync(0xffffffffu, mx, o));
            float nm    = fmaxf(mi[i], mx);
            float alpha = __expf(mi[i] - nm);
            float rs = 0.f;
            #pragma unroll
            for (int j = 0; j < 4; j++) {
                float p = __expf(s[i][j] - nm);
                s[i][j] = p;
                rs += p;
            }
            #pragma unroll
            for (int o = 1; o < 16; o <<= 1)
                rs += __shfl_xor_sync(0xffffffffu, rs, o);
            li[i] = li[i] * alpha + rs;
            mi[i] = nm;
            #pragma unroll
            for (int j = 0; j < 4; j++) acc[i][j] *= alpha;
        }

        // Stage P
        #pragma unroll
        for (int i = 0; i < 4; i++)
            #pragma unroll
            for (int j = 0; j < 4; j++)
                Ps[(r0 + i) * 65 + (c0 + j)] = s[i][j];
        __syncthreads();

        // O += P * V (thread: rows r0..r0+3, dh-cols c0..c0+3)
        #pragma unroll 8
        for (int kk = 0; kk < 64; kk++) {
            float ap[4], bv[4];
            #pragma unroll
            for (int i = 0; i < 4; i++) ap[i] = Ps[(r0 + i) * 65 + kk];
            #pragma unroll
            for (int j = 0; j < 4; j++) bv[j] = Vs[kk * 65 + (c0 + j)];
            #pragma unroll
            for (int i = 0; i < 4; i++)
                #pragma unroll
                for (int j = 0; j < 4; j++)
                    acc[i][j] += ap[i] * bv[j];
        }
        __syncthreads();
    }

    // Write z[b, s, h, dh]
    #pragma unroll
    for (int i = 0; i < 4; i++) {
        float inv = 1.f / li[i];
        size_t rbase = base + (size_t)(qt * 64 + r0 + i) * D_;
        #pragma unroll
        for (int j = 0; j < 4; j++)
            z[rbase + c0 + j] = acc[i][j] * inv;
    }
}

// ---------------- Host launch ----------------
static float* sym_addr(const void* sym) {
    void* p = nullptr;
    cudaGetSymbolAddress(&p, sym);
    return (float*)p;
}

extern "C" void kernel_launch(void* const* d_in, const int* in_sizes, int n_in,
                              void* d_out, int out_size) {
    const float* x     = (const float*)d_in[0];
    const float* W_Q   = (const float*)d_in[1];
    const float* W_K   = (const float*)d_in[2];
    const float* W_V   = (const float*)d_in[3];
    const float* W_O   = (const float*)d_in[4];
    const float* b_Q   = (const float*)d_in[5];
    const float* b_K   = (const float*)d_in[6];
    const float* b_V   = (const float*)d_in[7];
    const float* b_O   = (const float*)d_in[8];
    const float* W_in  = (const float*)d_in[9];
    const float* b_in  = (const float*)d_in[10];
    const float* W_out = (const float*)d_in[11];
    const float* b_out = (const float*)d_in[12];
    float* out = (float*)d_out;

    float* xn    = sym_addr(g_xn);
    float* qb    = sym_addr(g_q);
    float* kb    = sym_addr(g_k);
    float* vb    = sym_addr(g_v);
    float* zb    = sym_addr(g_z);
    float* rmid  = sym_addr(g_rmid);
    float* mln   = sym_addr(g_mln);
    float* hid   = sym_addr(g_hid);
    float* WqT   = sym_addr(g_WqT);
    float* WkT   = sym_addr(g_WkT);
    float* WvT   = sym_addr(g_WvT);
    float* WoT   = sym_addr(g_WoT);
    float* WinT  = sym_addr(g_WinT);
    float* WoutT = sym_addr(g_WoutT);

    dim3 tb(32, 32);
    // Weight transposes to [K,N]
    transpose_kernel<<<dim3(D_ / 32, D_ / 32), tb>>>(W_Q, WqT, D_, D_);
    transpose_kernel<<<dim3(D_ / 32, D_ / 32), tb>>>(W_K, WkT, D_, D_);
    transpose_kernel<<<dim3(D_ / 32, D_ / 32), tb>>>(W_V, WvT, D_, D_);
    transpose_wo_kernel<<<(D_ * D_) / 256, 256>>>(W_O, WoT);
    transpose_kernel<<<dim3(D_ / 32, DM_ / 32), tb>>>(W_in,  WinT,  DM_, D_);
    transpose_kernel<<<dim3(DM_ / 32, D_ / 32), tb>>>(W_out, WoutT, D_, DM_);

    // LN(x) -> xn
    ln_kernel<<<T_, 256>>>(x, xn);

    // Q/K/V projections
    dim3 gQKV(D_ / 128, T_ / 128);     // (8, 32)
    sgemm_kernel<0, 0><<<gQKV, 256>>>(T_, D_, D_, xn, WqT, b_Q, nullptr, qb);
    sgemm_kernel<0, 0><<<gQKV, 256>>>(T_, D_, D_, xn, WkT, b_K, nullptr, kb);
    sgemm_kernel<0, 0><<<gQKV, 256>>>(T_, D_, D_, xn, WvT, b_V, nullptr, vb);

    // Attention
    int attn_smem = 4 * 64 * 65 * (int)sizeof(float);   // 66560 B
    cudaFuncSetAttribute(attn_kernel, cudaFuncAttributeMaxDynamicSharedMemorySize, attn_smem);
    attn_kernel<<<dim3(S_ / 64, B_ * H_), 256, attn_smem>>>(qb, kb, vb, zb);

    // Output projection + residual: resid_mid = x + (z @ WoT + b_O)
    sgemm_kernel<0, 1><<<gQKV, 256>>>(T_, D_, D_, zb, WoT, b_O, x, rmid);

    // LN(resid_mid) -> mln
    ln_kernel<<<T_, 256>>>(rmid, mln);

    // MLP in (fused gelu): hid = gelu(mln @ WinT + b_in)
    dim3 gIN(DM_ / 128, T_ / 128);     // (32, 32)
    sgemm_kernel<1, 0><<<gIN, 256>>>(T_, DM_, D_, mln, WinT, b_in, nullptr, hid);

    // MLP out + residual: out = resid_mid + (hid @ WoutT + b_out)
    dim3 gOUT(D_ / 128, T_ / 128);     // (8, 32)
    sgemm_kernel<0, 1><<<gOUT, 256>>>(T_, D_, DM_, hid, WoutT, b_out, rmid, out);
}

// round 12
// speedup vs baseline: 1.4853x; 1.4853x over previous
#include <cuda_runtime.h>
#include <cuda_bf16.h>
#include <math.h>
#include <stdint.h>

// ---------------- Problem dims ----------------
#define B_      2
#define S_      2048
#define T_      4096          // B*S tokens
#define D_      1024
#define H_      16
#define DH_     64
#define DM_     4096
#define EPSV    1e-5f
#define IGNOREV -100000.0f

// ---------------- Small helpers ----------------
__device__ __forceinline__ uint32_t smem_u32(const void* p) {
    uint32_t a;
    asm("{ .reg .u64 t; cvta.to.shared.u64 t, %1; cvt.u32.u64 %0, t; }" : "=r"(a) : "l"(p));
    return a;
}
__device__ __forceinline__ void split2(float v, __nv_bfloat16& h, __nv_bfloat16& l) {
    h = __float2bfloat16(v);
    l = __float2bfloat16(v - __bfloat162float(h));
}
__device__ __forceinline__ float gelu_new_f(float x) {
    float x3 = x * x * x;
    return 0.5f * x * (1.0f + tanhf(0.7978845608028654f * (x + 0.044715f * x3)));
}

// ---------------- Baseline-PTX tensor-core primitives (sm_80+; valid on sm_103) ----
__device__ __forceinline__ void cp16(uint32_t saddr, const void* g) {
    asm volatile("cp.async.cg.shared.global [%0], [%1], 16;" :: "r"(saddr), "l"(g));
}
__device__ __forceinline__ void cp_commit() {
    asm volatile("cp.async.commit_group;" ::: "memory");
}
template <int N>
__device__ __forceinline__ void cp_wait() {
    asm volatile("cp.async.wait_group %0;" :: "n"(N) : "memory");
}
__device__ __forceinline__ void ldsm4(uint32_t (&r)[4], uint32_t a) {
    asm volatile("ldmatrix.sync.aligned.m8n8.x4.shared.b16 {%0,%1,%2,%3}, [%4];"
                 : "=r"(r[0]), "=r"(r[1]), "=r"(r[2]), "=r"(r[3]) : "r"(a));
}
__device__ __forceinline__ void mma16816(float (&c)[4], const uint32_t (&a)[4],
                                         uint32_t b0, uint32_t b1) {
    asm volatile(
        "mma.sync.aligned.m16n8k16.row.col.f32.bf16.bf16.f32 "
        "{%0,%1,%2,%3}, {%4,%5,%6,%7}, {%8,%9}, {%0,%1,%2,%3};"
        : "+f"(c[0]), "+f"(c[1]), "+f"(c[2]), "+f"(c[3])
        : "r"(a[0]), "r"(a[1]), "r"(a[2]), "r"(a[3]), "r"(b0), "r"(b1));
}

// ---------------- Scratch (static device globals; no allocation) ----------------
__device__ __nv_bfloat16 g_xn_hi [T_ * D_];
__device__ __nv_bfloat16 g_xn_lo [T_ * D_];
__device__ float         g_qkv   [(size_t)T_ * 3072];
__device__ __nv_bfloat16 g_z_hi  [T_ * D_];
__device__ __nv_bfloat16 g_z_lo  [T_ * D_];
__device__ float         g_rmid  [T_ * D_];
__device__ __nv_bfloat16 g_m_hi  [T_ * D_];
__device__ __nv_bfloat16 g_m_lo  [T_ * D_];
__device__ __nv_bfloat16 g_hid_hi[(size_t)T_ * DM_];
__device__ __nv_bfloat16 g_hid_lo[(size_t)T_ * DM_];
__device__ __nv_bfloat16 g_Wqkv_hi[3 * D_ * D_];
__device__ __nv_bfloat16 g_Wqkv_lo[3 * D_ * D_];
__device__ __nv_bfloat16 g_Wo_hi [D_ * D_];
__device__ __nv_bfloat16 g_Wo_lo [D_ * D_];
__device__ __nv_bfloat16 g_Win_hi[(size_t)DM_ * D_];
__device__ __nv_bfloat16 g_Win_lo[(size_t)DM_ * D_];
__device__ __nv_bfloat16 g_Wout_hi[(size_t)D_ * DM_];
__device__ __nv_bfloat16 g_Wout_lo[(size_t)D_ * DM_];
__device__ float         g_bqkv  [3072];

// ---------------- Weight split (contiguous [N,K] fp32 -> bf16 hi/lo) ----------------
__global__ void split_kernel(const float* __restrict__ src,
                             __nv_bfloat16* __restrict__ hi,
                             __nv_bfloat16* __restrict__ lo, int n4) {
    int i = blockIdx.x * 256 + threadIdx.x;
    if (i >= n4) return;
    float4 v = ((const float4*)src)[i];
    __nv_bfloat16 h0,h1,h2,h3,l0,l1,l2,l3;
    split2(v.x,h0,l0); split2(v.y,h1,l1); split2(v.z,h2,l2); split2(v.w,h3,l3);
    uint32_t ph0 = (uint32_t)__bfloat16_as_ushort(h0) | ((uint32_t)__bfloat16_as_ushort(h1) << 16);
    uint32_t ph1 = (uint32_t)__bfloat16_as_ushort(h2) | ((uint32_t)__bfloat16_as_ushort(h3) << 16);
    uint32_t pl0 = (uint32_t)__bfloat16_as_ushort(l0) | ((uint32_t)__bfloat16_as_ushort(l1) << 16);
    uint32_t pl1 = (uint32_t)__bfloat16_as_ushort(l2) | ((uint32_t)__bfloat16_as_ushort(l3) << 16);
    ((uint2*)hi)[i] = make_uint2(ph0, ph1);
    ((uint2*)lo)[i] = make_uint2(pl0, pl1);
}

// W_O [H, D, DH] -> [N=d][K=h*64+dh] bf16 hi/lo
__global__ void wo_split_kernel(const float* __restrict__ wo,
                                __nv_bfloat16* __restrict__ hi,
                                __nv_bfloat16* __restrict__ lo) {
    int idx = blockIdx.x * 256 + threadIdx.x;        // 1M elems
    int d  = idx >> 10;
    int kk = idx & 1023;
    int h  = kk >> 6, dh = kk & 63;
    float v = wo[(size_t)h * D_ * DH_ + (size_t)d * DH_ + dh];
    __nv_bfloat16 hh, ll; split2(v, hh, ll);
    hi[idx] = hh; lo[idx] = ll;
}

__global__ void bias_concat_kernel(const float* bq, const float* bk, const float* bv,
                                   float* dst) {
    int i = blockIdx.x * 256 + threadIdx.x;
    if (i < 1024) dst[i] = bq[i];
    else if (i < 2048) dst[i] = bk[i - 1024];
    else if (i < 3072) dst[i] = bv[i - 2048];
}

// ---------------- LayerNorm -> bf16 hi/lo ----------------
__global__ void ln_split_kernel(const float* __restrict__ src,
                                __nv_bfloat16* __restrict__ hi,
                                __nv_bfloat16* __restrict__ lo) {
    int row = blockIdx.x;
    float4 vv = ((const float4*)(src + (size_t)row * D_))[threadIdx.x];
    float s  = vv.x + vv.y + vv.z + vv.w;
    float s2 = vv.x*vv.x + vv.y*vv.y + vv.z*vv.z + vv.w*vv.w;
    #pragma unroll
    for (int o = 16; o > 0; o >>= 1) {
        s  += __shfl_xor_sync(0xffffffffu, s,  o);
        s2 += __shfl_xor_sync(0xffffffffu, s2, o);
    }
    __shared__ float ws[8], ws2[8];
    __shared__ float s_mean, s_r;
    int w = threadIdx.x >> 5;
    if ((threadIdx.x & 31) == 0) { ws[w] = s; ws2[w] = s2; }
    __syncthreads();
    if (threadIdx.x == 0) {
        float a = 0.f, b2 = 0.f;
        #pragma unroll
        for (int i = 0; i < 8; i++) { a += ws[i]; b2 += ws2[i]; }
        float mean = a * (1.f / D_);
        float var  = b2 * (1.f / D_) - mean * mean;
        s_mean = mean; s_r = rsqrtf(var + EPSV);
    }
    __syncthreads();
    float mean = s_mean, r = s_r;
    float o0 = (vv.x - mean) * r, o1 = (vv.y - mean) * r;
    float o2 = (vv.z - mean) * r, o3 = (vv.w - mean) * r;
    __nv_bfloat16 h0,h1,h2,h3,l0,l1,l2,l3;
    split2(o0,h0,l0); split2(o1,h1,l1); split2(o2,h2,l2); split2(o3,h3,l3);
    uint32_t ph0 = (uint32_t)__bfloat16_as_ushort(h0) | ((uint32_t)__bfloat16_as_ushort(h1) << 16);
    uint32_t ph1 = (uint32_t)__bfloat16_as_ushort(h2) | ((uint32_t)__bfloat16_as_ushort(h3) << 16);
    uint32_t pl0 = (uint32_t)__bfloat16_as_ushort(l0) | ((uint32_t)__bfloat16_as_ushort(l1) << 16);
    uint32_t pl1 = (uint32_t)__bfloat16_as_ushort(l2) | ((uint32_t)__bfloat16_as_ushort(l3) << 16);
    size_t base = (size_t)row * D_ + threadIdx.x * 4;
    ((uint2*)(hi + base))[0] = make_uint2(ph0, ph1);
    ((uint2*)(lo + base))[0] = make_uint2(pl0, pl1);
}

// ================= mma.sync bf16-split GEMM =================
// C[M,N] = epi( (Ahi+Alo)[M,K] @ (Bhi+Blo)[N,K]^T + bias[N] )
// CTA tile 128x128, BK=32, 8 warps (warp tile 32x64). 3 products: hi*hi + hi*lo + lo*hi.
#define GSM_STRIDE 40                     // bf16 per padded row (80 B; 5 super-banks, coprime 8)
#define GSM_ARR_B  (128 * GSM_STRIDE * 2) // 10240 bytes per array
#define GSM_STAGE_B (4 * GSM_ARR_B)       // 40960 bytes per stage (Ahi,Alo,Bhi,Blo)
#define GEMM_SMEM  (2 * GSM_STAGE_B)      // 81920 bytes

__device__ __forceinline__ void fill_stage(
    uint32_t sbase,
    const __nv_bfloat16* __restrict__ Ahi, const __nv_bfloat16* __restrict__ Alo,
    const __nv_bfloat16* __restrict__ Bhi, const __nv_bfloat16* __restrict__ Blo,
    int m0, int n0, int kb, int K, int tid) {
    int row = tid & 127;
    int kc0 = tid >> 7;                   // 0 or 1
    #pragma unroll
    for (int i = 0; i < 2; ++i) {
        int kc = kc0 + i * 2;             // 0..3 (4 chunks of 8 bf16 = 32 K elems)
        uint32_t soff = (uint32_t)(row * GSM_STRIDE + kc * 8) * 2;
        size_t ga = (size_t)(m0 + row) * K + kb + kc * 8;
        size_t gb = (size_t)(n0 + row) * K + kb + kc * 8;
        cp16(sbase +                 soff, Ahi + ga);
        cp16(sbase + GSM_ARR_B +     soff, Alo + ga);
        cp16(sbase + 2 * GSM_ARR_B + soff, Bhi + gb);
        cp16(sbase + 3 * GSM_ARR_B + soff, Blo + gb);
    }
}

template <int ACT, int RES, int OUTBF16>
__global__ void __launch_bounds__(256, 1)
gemm_mma(int M, int N, int K,
         const __nv_bfloat16* __restrict__ Ahi, const __nv_bfloat16* __restrict__ Alo,
         const __nv_bfloat16* __restrict__ Bhi, const __nv_bfloat16* __restrict__ Blo,
         const float* __restrict__ bias, const float* __restrict__ resid,
         float* __restrict__ Cf,
         __nv_bfloat16* __restrict__ Chi, __nv_bfloat16* __restrict__ Clo) {
    extern __shared__ char sm_raw[];
    uint32_t sb = smem_u32(sm_raw);
    const int tid  = threadIdx.x;
    const int wid  = tid >> 5;
    const int lane = tid & 31;
    const int m0 = blockIdx.y * 128;
    const int n0 = blockIdx.x * 128;
    const int wr0 = (wid >> 1) * 32;      // warp row offset (4 groups)
    const int wc0 = (wid & 1) * 64;       // warp col offset (2 groups)

    float acc[2][8][4];
    #pragma unroll
    for (int mt = 0; mt < 2; ++mt)
        #pragma unroll
        for (int j = 0; j < 8; ++j)
            #pragma unroll
            for (int q = 0; q < 4; ++q) acc[mt][j][q] = 0.f;

    const int nst = K >> 5;
    fill_stage(sb, Ahi, Alo, Bhi, Blo, m0, n0, 0, K, tid);
    cp_commit();

    for (int c = 0; c < nst; ++c) {
        if (c + 1 < nst) {
            fill_stage(sb + (uint32_t)((c + 1) & 1) * GSM_STAGE_B,
                       Ahi, Alo, Bhi, Blo, m0, n0, (c + 1) << 5, K, tid);
            cp_commit();
            cp_wait<1>();
        } else {
            cp_wait<0>();
        }
        __syncthreads();

        uint32_t st = sb + (uint32_t)(c & 1) * GSM_STAGE_B;
        #pragma unroll
        for (int ks = 0; ks < 2; ++ks) {
            const int k0 = ks * 16;
            uint32_t Ah[2][4], Al[2][4];
            #pragma unroll
            for (int mt = 0; mt < 2; ++mt) {
                int arow = wr0 + mt * 16 + (lane & 15);
                uint32_t aoff = (uint32_t)(arow * GSM_STRIDE + k0 + ((lane >> 4) << 3)) * 2;
                ldsm4(Ah[mt], st + aoff);
                ldsm4(Al[mt], st + GSM_ARR_B + aoff);
            }
            uint32_t Bh[4][4], Bl[4][4];
            #pragma unroll
            for (int np = 0; np < 4; ++np) {
                int quad = lane >> 3;
                int brow = wc0 + np * 16 + ((quad >> 1) << 3) + (lane & 7);
                uint32_t boff = (uint32_t)(brow * GSM_STRIDE + k0 + ((quad & 1) << 3)) * 2;
                ldsm4(Bh[np], st + 2 * GSM_ARR_B + boff);
                ldsm4(Bl[np], st + 3 * GSM_ARR_B + boff);
            }
            #pragma unroll
            for (int mt = 0; mt < 2; ++mt)
                #pragma unroll
                for (int j = 0; j < 8; ++j) {
                    const int np = j >> 1;
                    const int hreg = (j & 1) << 1;        // 0 or 2
                    mma16816(acc[mt][j], Ah[mt], Bh[np][hreg], Bh[np][hreg + 1]);
                    mma16816(acc[mt][j], Ah[mt], Bl[np][hreg], Bl[np][hreg + 1]);
                    mma16816(acc[mt][j], Al[mt], Bh[np][hreg], Bh[np][hreg + 1]);
                }
        }
        __syncthreads();
    }

    // Epilogue: C frag: lane holds (row = t/4 [+8], col = (t%4)*2 + {0,1})
    const int qrow = lane >> 2;
    const int qcol = (lane & 3) * 2;
    #pragma unroll
    for (int mt = 0; mt < 2; ++mt)
        #pragma unroll
        for (int j = 0; j < 8; ++j)
            #pragma unroll
            for (int half = 0; half < 2; ++half) {
                int row = m0 + wr0 + mt * 16 + qrow + half * 8;
                int col = n0 + wc0 + j * 8 + qcol;
                float v0 = acc[mt][j][half * 2 + 0] + bias[col];
                float v1 = acc[mt][j][half * 2 + 1] + bias[col + 1];
                if (ACT) { v0 = gelu_new_f(v0); v1 = gelu_new_f(v1); }
                size_t off = (size_t)row * N + col;
                if (RES) {
                    float2 rr = *(const float2*)(resid + off);
                    v0 += rr.x; v1 += rr.y;
                }
                if (!OUTBF16) {
                    *(float2*)(Cf + off) = make_float2(v0, v1);
                } else {
                    __nv_bfloat16 h0, h1, l0, l1;
                    split2(v0, h0, l0);
                    split2(v1, h1, l1);
                    uint32_t ph = (uint32_t)__bfloat16_as_ushort(h0) |
                                  ((uint32_t)__bfloat16_as_ushort(h1) << 16);
                    uint32_t pl = (uint32_t)__bfloat16_as_ushort(l0) |
                                  ((uint32_t)__bfloat16_as_ushort(l1) << 16);
                    *(uint32_t*)(Chi + off) = ph;
                    *(uint32_t*)(Clo + off) = pl;
                }
            }
}

// ---------------- Causal flash attention (fp32), reads packed qkv, writes z hi/lo ----------------
__global__ void __launch_bounds__(256)
attn_kernel(const float* __restrict__ qkv,
            __nv_bfloat16* __restrict__ z_hi, __nv_bfloat16* __restrict__ z_lo) {
    extern __shared__ float sm[];
    float* Qs = sm;
    float* Ks = Qs + 64 * 65;
    float* Vs = Ks + 64 * 65;
    float* Ps = Vs + 64 * 65;

    int qt = blockIdx.x;
    int bh = blockIdx.y;
    int b = bh >> 4, h = bh & 15;
    int tid = threadIdx.x;
    int ty = tid >> 4, tx = tid & 15;
    int r0 = ty * 4, c0 = tx * 4;

    const float* qp = qkv + (size_t)b * S_ * 3072 + h * 64;          // row stride 3072
    const float* kp = qp + 1024;
    const float* vp = qp + 2048;

    for (int i = tid; i < 64 * 16; i += 256) {
        int row = i >> 4, c4 = (i & 15) * 4;
        float4 t = *(const float4*)(qp + (size_t)(qt * 64 + row) * 3072 + c4);
        float* dst = Qs + row * 65 + c4;
        dst[0] = t.x; dst[1] = t.y; dst[2] = t.z; dst[3] = t.w;
    }

    float mi[4], li[4], acc[4][4];
    #pragma unroll
    for (int i = 0; i < 4; i++) {
        mi[i] = -1e30f; li[i] = 0.f;
        #pragma unroll
        for (int j = 0; j < 4; j++) acc[i][j] = 0.f;
    }

    for (int jt = 0; jt <= qt; jt++) {
        for (int i = tid; i < 64 * 16; i += 256) {
            int row = i >> 4, c4 = (i & 15) * 4;
            size_t goff = (size_t)(jt * 64 + row) * 3072 + c4;
            float4 tk = *(const float4*)(kp + goff);
            float4 tv = *(const float4*)(vp + goff);
            float* dk = Ks + row * 65 + c4;
            float* dv = Vs + row * 65 + c4;
            dk[0] = tk.x; dk[1] = tk.y; dk[2] = tk.z; dk[3] = tk.w;
            dv[0] = tv.x; dv[1] = tv.y; dv[2] = tv.z; dv[3] = tv.w;
        }
        __syncthreads();

        float s[4][4];
        #pragma unroll
        for (int i = 0; i < 4; i++)
            #pragma unroll
            for (int j = 0; j < 4; j++) s[i][j] = 0.f;

        #pragma unroll 8
        for (int kk = 0; kk < 64; kk++) {
            float aq[4], bk[4];
            #pragma unroll
            for (int i = 0; i < 4; i++) aq[i] = Qs[(r0 + i) * 65 + kk];
            #pragma unroll
            for (int j = 0; j < 4; j++) bk[j] = Ks[(c0 + j) * 65 + kk];
            #pragma unroll
            for (int i = 0; i < 4; i++)
                #pragma unroll
                for (int j = 0; j < 4; j++) s[i][j] += aq[i] * bk[j];
        }

        #pragma unroll
        for (int i = 0; i < 4; i++)
            #pragma unroll
            for (int j = 0; j < 4; j++) {
                s[i][j] *= 0.125f;
                if (jt == qt && (c0 + j) > (r0 + i)) s[i][j] = IGNOREV;
            }

        #pragma unroll
        for (int i = 0; i < 4; i++) {
            float mx = fmaxf(fmaxf(s[i][0], s[i][1]), fmaxf(s[i][2], s[i][3]));
            #pragma unroll
            for (int o = 1; o < 16; o <<= 1)
                mx = fmaxf(mx, __shfl_xor_sync(0xffffffffu, mx, o));
            float nm    = fmaxf(mi[i], mx);
            float alpha = __expf(mi[i] - nm);
            float rs = 0.f;
            #pragma unroll
            for (int j = 0; j < 4; j++) {
                float p = __expf(s[i][j] - nm);
                s[i][j] = p; rs += p;
            }
            #pragma unroll
            for (int o = 1; o < 16; o <<= 1)
                rs += __shfl_xor_sync(0xffffffffu, rs, o);
            li[i] = li[i] * alpha + rs;
            mi[i] = nm;
            #pragma unroll
            for (int j = 0; j < 4; j++) acc[i][j] *= alpha;
        }

        #pragma unroll
        for (int i = 0; i < 4; i++)
            #pragma unroll
            for (int j = 0; j < 4; j++)
                Ps[(r0 + i) * 65 + (c0 + j)] = s[i][j];
        __syncthreads();

        #pragma unroll 8
        for (int kk = 0; kk < 64; kk++) {
            float ap[4], bv[4];
            #pragma unroll
            for (int i = 0; i < 4; i++) ap[i] = Ps[(r0 + i) * 65 + kk];
            #pragma unroll
            for (int j = 0; j < 4; j++) bv[j] = Vs[kk * 65 + (c0 + j)];
            #pragma unroll
            for (int i = 0; i < 4; i++)
                #pragma unroll
                for (int j = 0; j < 4; j++)
                    acc[i][j] += ap[i] * bv[j];
        }
        __syncthreads();
    }

    #pragma unroll
    for (int i = 0; i < 4; i++) {
        float inv = 1.f / li[i];
        size_t rbase = ((size_t)b * S_ + qt * 64 + r0 + i) * D_ + h * 64;
        #pragma unroll
        for (int j = 0; j < 4; j++) {
            float v = acc[i][j] * inv;
            __nv_bfloat16 hh, ll; split2(v, hh, ll);
            z_hi[rbase + c0 + j] = hh;
            z_lo[rbase + c0 + j] = ll;
        }
    }
}

// ---------------- Host launch ----------------
template <typename Tp>
static Tp* sym_addr(const void* sym) {
    void* p = nullptr;
    cudaGetSymbolAddress(&p, sym);
    return (Tp*)p;
}

extern "C" void kernel_launch(void* const* d_in, const int* in_sizes, int n_in,
                              void* d_out, int out_size) {
    const float* x     = (const float*)d_in[0];
    const float* W_Q   = (const float*)d_in[1];
    const float* W_K   = (const float*)d_in[2];
    const float* W_V   = (const float*)d_in[3];
    const float* W_O   = (const float*)d_in[4];
    const float* b_Q   = (const float*)d_in[5];
    const float* b_K   = (const float*)d_in[6];
    const float* b_V   = (const float*)d_in[7];
    const float* b_O   = (const float*)d_in[8];
    const float* W_in  = (const float*)d_in[9];
    const float* b_in  = (const float*)d_in[10];
    const float* W_out = (const float*)d_in[11];
    const float* b_out = (const float*)d_in[12];
    float* out = (float*)d_out;

    __nv_bfloat16* xn_hi  = sym_addr<__nv_bfloat16>(g_xn_hi);
    __nv_bfloat16* xn_lo  = sym_addr<__nv_bfloat16>(g_xn_lo);
    float*         qkv    = sym_addr<float>(g_qkv);
    __nv_bfloat16* z_hi   = sym_addr<__nv_bfloat16>(g_z_hi);
    __nv_bfloat16* z_lo   = sym_addr<__nv_bfloat16>(g_z_lo);
    float*         rmid   = sym_addr<float>(g_rmid);
    __nv_bfloat16* m_hi   = sym_addr<__nv_bfloat16>(g_m_hi);
    __nv_bfloat16* m_lo   = sym_addr<__nv_bfloat16>(g_m_lo);
    __nv_bfloat16* hid_hi = sym_addr<__nv_bfloat16>(g_hid_hi);
    __nv_bfloat16* hid_lo = sym_addr<__nv_bfloat16>(g_hid_lo);
    __nv_bfloat16* Wqkv_hi = sym_addr<__nv_bfloat16>(g_Wqkv_hi);
    __nv_bfloat16* Wqkv_lo = sym_addr<__nv_bfloat16>(g_Wqkv_lo);
    __nv_bfloat16* Wo_hi   = sym_addr<__nv_bfloat16>(g_Wo_hi);
    __nv_bfloat16* Wo_lo   = sym_addr<__nv_bfloat16>(g_Wo_lo);
    __nv_bfloat16* Win_hi  = sym_addr<__nv_bfloat16>(g_Win_hi);
    __nv_bfloat16* Win_lo  = sym_addr<__nv_bfloat16>(g_Win_lo);
    __nv_bfloat16* Wout_hi = sym_addr<__nv_bfloat16>(g_Wout_hi);
    __nv_bfloat16* Wout_lo = sym_addr<__nv_bfloat16>(g_Wout_lo);
    float*         bqkv    = sym_addr<float>(g_bqkv);

    // Opt-in dynamic smem (no-op after first call)
    cudaFuncSetAttribute(gemm_mma<0,0,0>, cudaFuncAttributeMaxDynamicSharedMemorySize, GEMM_SMEM);
    cudaFuncSetAttribute(gemm_mma<0,1,0>, cudaFuncAttributeMaxDynamicSharedMemorySize, GEMM_SMEM);
    cudaFuncSetAttribute(gemm_mma<1,0,1>, cudaFuncAttributeMaxDynamicSharedMemorySize, GEMM_SMEM);
    int attn_smem = 4 * 64 * 65 * (int)sizeof(float);
    cudaFuncSetAttribute(attn_kernel, cudaFuncAttributeMaxDynamicSharedMemorySize, attn_smem);

    // Weight splits
    const int NW1 = (D_ * D_) / 4;
    split_kernel<<<(NW1 + 255) / 256, 256>>>(W_Q, Wqkv_hi,               Wqkv_lo,               NW1);
    split_kernel<<<(NW1 + 255) / 256, 256>>>(W_K, Wqkv_hi + D_ * D_,     Wqkv_lo + D_ * D_,     NW1);
    split_kernel<<<(NW1 + 255) / 256, 256>>>(W_V, Wqkv_hi + 2 * D_ * D_, Wqkv_lo + 2 * D_ * D_, NW1);
    wo_split_kernel<<<(D_ * D_) / 256, 256>>>(W_O, Wo_hi, Wo_lo);
    const int NW2 = (DM_ * D_) / 4;
    split_kernel<<<(NW2 + 255) / 256, 256>>>(W_in,  Win_hi,  Win_lo,  NW2);
    split_kernel<<<(NW2 + 255) / 256, 256>>>(W_out, Wout_hi, Wout_lo, NW2);
    bias_concat_kernel<<<12, 256>>>(b_Q, b_K, b_V, bqkv);

    // LN1 -> xn hi/lo
    ln_split_kernel<<<T_, 256>>>(x, xn_hi, xn_lo);

    // Fused QKV projection: qkv[T,3072]
    gemm_mma<0,0,0><<<dim3(3072 / 128, T_ / 128), 256, GEMM_SMEM>>>(
        T_, 3072, D_, xn_hi, xn_lo, Wqkv_hi, Wqkv_lo, bqkv, nullptr, qkv, nullptr, nullptr);

    // Attention -> z hi/lo
    attn_kernel<<<dim3(S_ / 64, B_ * H_), 256, attn_smem>>>(qkv, z_hi, z_lo);

    // O projection + residual: rmid = x + z @ Wo^T + b_O
    gemm_mma<0,1,0><<<dim3(D_ / 128, T_ / 128), 256, GEMM_SMEM>>>(
        T_, D_, D_, z_hi, z_lo, Wo_hi, Wo_lo, b_O, x, rmid, nullptr, nullptr);

    // LN2 -> m hi/lo
    ln_split_kernel<<<T_, 256>>>(rmid, m_hi, m_lo);

    // MLP in + gelu -> hid hi/lo (bf16 split output)
    gemm_mma<1,0,1><<<dim3(DM_ / 128, T_ / 128), 256, GEMM_SMEM>>>(
        T_, DM_, D_, m_hi, m_lo, Win_hi, Win_lo, b_in, nullptr, nullptr, hid_hi, hid_lo);

    // MLP out + residual -> final output
    gemm_mma<0,1,0><<<dim3(D_ / 128, T_ / 128), 256, GEMM_SMEM>>>(
        T_, D_, DM_, hid_hi, hid_lo, Wout_hi, Wout_lo, b_out, rmid, out, nullptr, nullptr);
}

// round 14
// speedup vs baseline: 1.7653x; 1.1885x over previous
#include <cuda_runtime.h>
#include <cuda_bf16.h>
#include <math.h>
#include <stdint.h>

// ---------------- Problem dims ----------------
#define B_      2
#define S_      2048
#define T_      4096          // B*S tokens
#define D_      1024
#define H_      16
#define DH_     64
#define DM_     4096
#define EPSV    1e-5f
#define IGNOREV -100000.0f

// ---------------- Small helpers ----------------
__device__ __forceinline__ uint32_t smem_u32(const void* p) {
    uint32_t a;
    asm("{ .reg .u64 t; cvta.to.shared.u64 t, %1; cvt.u32.u64 %0, t; }" : "=r"(a) : "l"(p));
    return a;
}
__device__ __forceinline__ void split2(float v, __nv_bfloat16& h, __nv_bfloat16& l) {
    h = __float2bfloat16(v);
    l = __float2bfloat16(v - __bfloat162float(h));
}
__device__ __forceinline__ float gelu_new_f(float x) {
    float x3 = x * x * x;
    return 0.5f * x * (1.0f + tanhf(0.7978845608028654f * (x + 0.044715f * x3)));
}

// ---------------- Baseline-PTX tensor-core primitives (sm_80+; valid on sm_103) ----
__device__ __forceinline__ void cp16(uint32_t saddr, const void* g) {
    asm volatile("cp.async.cg.shared.global [%0], [%1], 16;" :: "r"(saddr), "l"(g));
}
__device__ __forceinline__ void cp_commit() {
    asm volatile("cp.async.commit_group;" ::: "memory");
}
template <int N>
__device__ __forceinline__ void cp_wait() {
    asm volatile("cp.async.wait_group %0;" :: "n"(N) : "memory");
}
__device__ __forceinline__ void ldsm4(uint32_t (&r)[4], uint32_t a) {
    asm volatile("ldmatrix.sync.aligned.m8n8.x4.shared.b16 {%0,%1,%2,%3}, [%4];"
                 : "=r"(r[0]), "=r"(r[1]), "=r"(r[2]), "=r"(r[3]) : "r"(a));
}
__device__ __forceinline__ void ldsm4t(uint32_t (&r)[4], uint32_t a) {
    asm volatile("ldmatrix.sync.aligned.m8n8.x4.trans.shared.b16 {%0,%1,%2,%3}, [%4];"
                 : "=r"(r[0]), "=r"(r[1]), "=r"(r[2]), "=r"(r[3]) : "r"(a));
}
__device__ __forceinline__ void mma16816(float (&c)[4], const uint32_t (&a)[4],
                                         uint32_t b0, uint32_t b1) {
    asm volatile(
        "mma.sync.aligned.m16n8k16.row.col.f32.bf16.bf16.f32 "
        "{%0,%1,%2,%3}, {%4,%5,%6,%7}, {%8,%9}, {%0,%1,%2,%3};"
        : "+f"(c[0]), "+f"(c[1]), "+f"(c[2]), "+f"(c[3])
        : "r"(a[0]), "r"(a[1]), "r"(a[2]), "r"(a[3]), "r"(b0), "r"(b1));
}

// ---------------- Scratch (static device globals; no allocation) ----------------
__device__ __nv_bfloat16 g_xn_hi [T_ * D_];
__device__ __nv_bfloat16 g_xn_lo [T_ * D_];
__device__ float         g_qkv   [(size_t)T_ * 3072];
__device__ __nv_bfloat16 g_z_hi  [T_ * D_];
__device__ __nv_bfloat16 g_z_lo  [T_ * D_];
__device__ float         g_rmid  [T_ * D_];
__device__ __nv_bfloat16 g_m_hi  [T_ * D_];
__device__ __nv_bfloat16 g_m_lo  [T_ * D_];
__device__ __nv_bfloat16 g_hid_hi[(size_t)T_ * DM_];
__device__ __nv_bfloat16 g_hid_lo[(size_t)T_ * DM_];
__device__ __nv_bfloat16 g_Wqkv_hi[3 * D_ * D_];
__device__ __nv_bfloat16 g_Wqkv_lo[3 * D_ * D_];
__device__ __nv_bfloat16 g_Wo_hi [D_ * D_];
__device__ __nv_bfloat16 g_Wo_lo [D_ * D_];
__device__ __nv_bfloat16 g_Win_hi[(size_t)DM_ * D_];
__device__ __nv_bfloat16 g_Win_lo[(size_t)DM_ * D_];
__device__ __nv_bfloat16 g_Wout_hi[(size_t)D_ * DM_];
__device__ __nv_bfloat16 g_Wout_lo[(size_t)D_ * DM_];
__device__ float         g_bqkv  [3072];

// ---------------- Weight split (contiguous [N,K] fp32 -> bf16 hi/lo) ----------------
__global__ void split_kernel(const float* __restrict__ src,
                             __nv_bfloat16* __restrict__ hi,
                             __nv_bfloat16* __restrict__ lo, int n4) {
    int i = blockIdx.x * 256 + threadIdx.x;
    if (i >= n4) return;
    float4 v = ((const float4*)src)[i];
    __nv_bfloat16 h0,h1,h2,h3,l0,l1,l2,l3;
    split2(v.x,h0,l0); split2(v.y,h1,l1); split2(v.z,h2,l2); split2(v.w,h3,l3);
    uint32_t ph0 = (uint32_t)__bfloat16_as_ushort(h0) | ((uint32_t)__bfloat16_as_ushort(h1) << 16);
    uint32_t ph1 = (uint32_t)__bfloat16_as_ushort(h2) | ((uint32_t)__bfloat16_as_ushort(h3) << 16);
    uint32_t pl0 = (uint32_t)__bfloat16_as_ushort(l0) | ((uint32_t)__bfloat16_as_ushort(l1) << 16);
    uint32_t pl1 = (uint32_t)__bfloat16_as_ushort(l2) | ((uint32_t)__bfloat16_as_ushort(l3) << 16);
    ((uint2*)hi)[i] = make_uint2(ph0, ph1);
    ((uint2*)lo)[i] = make_uint2(pl0, pl1);
}

// W_O [H, D, DH] -> [N=d][K=h*64+dh] bf16 hi/lo
__global__ void wo_split_kernel(const float* __restrict__ wo,
                                __nv_bfloat16* __restrict__ hi,
                                __nv_bfloat16* __restrict__ lo) {
    int idx = blockIdx.x * 256 + threadIdx.x;        // 1M elems
    int d  = idx >> 10;
    int kk = idx & 1023;
    int h  = kk >> 6, dh = kk & 63;
    float v = wo[(size_t)h * D_ * DH_ + (size_t)d * DH_ + dh];
    __nv_bfloat16 hh, ll; split2(v, hh, ll);
    hi[idx] = hh; lo[idx] = ll;
}

__global__ void bias_concat_kernel(const float* bq, const float* bk, const float* bv,
                                   float* dst) {
    int i = blockIdx.x * 256 + threadIdx.x;
    if (i < 1024) dst[i] = bq[i];
    else if (i < 2048) dst[i] = bk[i - 1024];
    else if (i < 3072) dst[i] = bv[i - 2048];
}

// ---------------- LayerNorm -> bf16 hi/lo ----------------
__global__ void ln_split_kernel(const float* __restrict__ src,
                                __nv_bfloat16* __restrict__ hi,
                                __nv_bfloat16* __restrict__ lo) {
    int row = blockIdx.x;
    float4 vv = ((const float4*)(src + (size_t)row * D_))[threadIdx.x];
    float s  = vv.x + vv.y + vv.z + vv.w;
    float s2 = vv.x*vv.x + vv.y*vv.y + vv.z*vv.z + vv.w*vv.w;
    #pragma unroll
    for (int o = 16; o > 0; o >>= 1) {
        s  += __shfl_xor_sync(0xffffffffu, s,  o);
        s2 += __shfl_xor_sync(0xffffffffu, s2, o);
    }
    __shared__ float ws[8], ws2[8];
    __shared__ float s_mean, s_r;
    int w = threadIdx.x >> 5;
    if ((threadIdx.x & 31) == 0) { ws[w] = s; ws2[w] = s2; }
    __syncthreads();
    if (threadIdx.x == 0) {
        float a = 0.f, b2 = 0.f;
        #pragma unroll
        for (int i = 0; i < 8; i++) { a += ws[i]; b2 += ws2[i]; }
        float mean = a * (1.f / D_);
        float var  = b2 * (1.f / D_) - mean * mean;
        s_mean = mean; s_r = rsqrtf(var + EPSV);
    }
    __syncthreads();
    float mean = s_mean, r = s_r;
    float o0 = (vv.x - mean) * r, o1 = (vv.y - mean) * r;
    float o2 = (vv.z - mean) * r, o3 = (vv.w - mean) * r;
    __nv_bfloat16 h0,h1,h2,h3,l0,l1,l2,l3;
    split2(o0,h0,l0); split2(o1,h1,l1); split2(o2,h2,l2); split2(o3,h3,l3);
    uint32_t ph0 = (uint32_t)__bfloat16_as_ushort(h0) | ((uint32_t)__bfloat16_as_ushort(h1) << 16);
    uint32_t ph1 = (uint32_t)__bfloat16_as_ushort(h2) | ((uint32_t)__bfloat16_as_ushort(h3) << 16);
    uint32_t pl0 = (uint32_t)__bfloat16_as_ushort(l0) | ((uint32_t)__bfloat16_as_ushort(l1) << 16);
    uint32_t pl1 = (uint32_t)__bfloat16_as_ushort(l2) | ((uint32_t)__bfloat16_as_ushort(l3) << 16);
    size_t base = (size_t)row * D_ + threadIdx.x * 4;
    ((uint2*)(hi + base))[0] = make_uint2(ph0, ph1);
    ((uint2*)(lo + base))[0] = make_uint2(pl0, pl1);
}

// ================= mma.sync bf16-split GEMM (unchanged from R12, verified) =========
#define GSM_STRIDE 40
#define GSM_ARR_B  (128 * GSM_STRIDE * 2)
#define GSM_STAGE_B (4 * GSM_ARR_B)
#define GEMM_SMEM  (2 * GSM_STAGE_B)

__device__ __forceinline__ void fill_stage(
    uint32_t sbase,
    const __nv_bfloat16* __restrict__ Ahi, const __nv_bfloat16* __restrict__ Alo,
    const __nv_bfloat16* __restrict__ Bhi, const __nv_bfloat16* __restrict__ Blo,
    int m0, int n0, int kb, int K, int tid) {
    int row = tid & 127;
    int kc0 = tid >> 7;
    #pragma unroll
    for (int i = 0; i < 2; ++i) {
        int kc = kc0 + i * 2;
        uint32_t soff = (uint32_t)(row * GSM_STRIDE + kc * 8) * 2;
        size_t ga = (size_t)(m0 + row) * K + kb + kc * 8;
        size_t gb = (size_t)(n0 + row) * K + kb + kc * 8;
        cp16(sbase +                 soff, Ahi + ga);
        cp16(sbase + GSM_ARR_B +     soff, Alo + ga);
        cp16(sbase + 2 * GSM_ARR_B + soff, Bhi + gb);
        cp16(sbase + 3 * GSM_ARR_B + soff, Blo + gb);
    }
}

template <int ACT, int RES, int OUTBF16>
__global__ void __launch_bounds__(256, 1)
gemm_mma(int M, int N, int K,
         const __nv_bfloat16* __restrict__ Ahi, const __nv_bfloat16* __restrict__ Alo,
         const __nv_bfloat16* __restrict__ Bhi, const __nv_bfloat16* __restrict__ Blo,
         const float* __restrict__ bias, const float* __restrict__ resid,
         float* __restrict__ Cf,
         __nv_bfloat16* __restrict__ Chi, __nv_bfloat16* __restrict__ Clo) {
    extern __shared__ char sm_raw[];
    uint32_t sb = smem_u32(sm_raw);
    const int tid  = threadIdx.x;
    const int wid  = tid >> 5;
    const int lane = tid & 31;
    const int m0 = blockIdx.y * 128;
    const int n0 = blockIdx.x * 128;
    const int wr0 = (wid >> 1) * 32;
    const int wc0 = (wid & 1) * 64;

    float acc[2][8][4];
    #pragma unroll
    for (int mt = 0; mt < 2; ++mt)
        #pragma unroll
        for (int j = 0; j < 8; ++j)
            #pragma unroll
            for (int q = 0; q < 4; ++q) acc[mt][j][q] = 0.f;

    const int nst = K >> 5;
    fill_stage(sb, Ahi, Alo, Bhi, Blo, m0, n0, 0, K, tid);
    cp_commit();

    for (int c = 0; c < nst; ++c) {
        if (c + 1 < nst) {
            fill_stage(sb + (uint32_t)((c + 1) & 1) * GSM_STAGE_B,
                       Ahi, Alo, Bhi, Blo, m0, n0, (c + 1) << 5, K, tid);
            cp_commit();
            cp_wait<1>();
        } else {
            cp_wait<0>();
        }
        __syncthreads();

        uint32_t st = sb + (uint32_t)(c & 1) * GSM_STAGE_B;
        #pragma unroll
        for (int ks = 0; ks < 2; ++ks) {
            const int k0 = ks * 16;
            uint32_t Ah[2][4], Al[2][4];
            #pragma unroll
            for (int mt = 0; mt < 2; ++mt) {
                int arow = wr0 + mt * 16 + (lane & 15);
                uint32_t aoff = (uint32_t)(arow * GSM_STRIDE + k0 + ((lane >> 4) << 3)) * 2;
                ldsm4(Ah[mt], st + aoff);
                ldsm4(Al[mt], st + GSM_ARR_B + aoff);
            }
            uint32_t Bh[4][4], Bl[4][4];
            #pragma unroll
            for (int np = 0; np < 4; ++np) {
                int quad = lane >> 3;
                int brow = wc0 + np * 16 + ((quad >> 1) << 3) + (lane & 7);
                uint32_t boff = (uint32_t)(brow * GSM_STRIDE + k0 + ((quad & 1) << 3)) * 2;
                ldsm4(Bh[np], st + 2 * GSM_ARR_B + boff);
                ldsm4(Bl[np], st + 3 * GSM_ARR_B + boff);
            }
            #pragma unroll
            for (int mt = 0; mt < 2; ++mt)
                #pragma unroll
                for (int j = 0; j < 8; ++j) {
                    const int np = j >> 1;
                    const int hreg = (j & 1) << 1;
                    mma16816(acc[mt][j], Ah[mt], Bh[np][hreg], Bh[np][hreg + 1]);
                    mma16816(acc[mt][j], Ah[mt], Bl[np][hreg], Bl[np][hreg + 1]);
                    mma16816(acc[mt][j], Al[mt], Bh[np][hreg], Bh[np][hreg + 1]);
                }
        }
        __syncthreads();
    }

    const int qrow = lane >> 2;
    const int qcol = (lane & 3) * 2;
    #pragma unroll
    for (int mt = 0; mt < 2; ++mt)
        #pragma unroll
        for (int j = 0; j < 8; ++j)
            #pragma unroll
            for (int half = 0; half < 2; ++half) {
                int row = m0 + wr0 + mt * 16 + qrow + half * 8;
                int col = n0 + wc0 + j * 8 + qcol;
                float v0 = acc[mt][j][half * 2 + 0] + bias[col];
                float v1 = acc[mt][j][half * 2 + 1] + bias[col + 1];
                if (ACT) { v0 = gelu_new_f(v0); v1 = gelu_new_f(v1); }
                size_t off = (size_t)row * N + col;
                if (RES) {
                    float2 rr = *(const float2*)(resid + off);
                    v0 += rr.x; v1 += rr.y;
                }
                if (!OUTBF16) {
                    *(float2*)(Cf + off) = make_float2(v0, v1);
                } else {
                    __nv_bfloat16 h0, h1, l0, l1;
                    split2(v0, h0, l0);
                    split2(v1, h1, l1);
                    uint32_t ph = (uint32_t)__bfloat16_as_ushort(h0) |
                                  ((uint32_t)__bfloat16_as_ushort(h1) << 16);
                    uint32_t pl = (uint32_t)__bfloat16_as_ushort(l0) |
                                  ((uint32_t)__bfloat16_as_ushort(l1) << 16);
                    *(uint32_t*)(Chi + off) = ph;
                    *(uint32_t*)(Clo + off) = pl;
                }
            }
}

// ================= Tensor-core causal flash attention (bf16 hi/lo split) ==========
// Grid: (32 qtiles reversed, 32 b*h). Block: 128 threads (4 warps, 16 q-rows each).
#define AT_STRIDE 72   // bf16 elems per padded smem row

// Load a 64x64 fp32 tile (row stride 3072) -> bf16 hi/lo smem (stride AT_STRIDE), scaled.
__device__ __forceinline__ void at_fill64(const float* __restrict__ src,
                                          __nv_bfloat16* __restrict__ hi,
                                          __nv_bfloat16* __restrict__ lo,
                                          int tid, float scale) {
    int row = tid >> 1;
    int c0  = (tid & 1) * 32;
    const float4* s4 = (const float4*)(src + (size_t)row * 3072 + c0);
    #pragma unroll
    for (int i = 0; i < 8; ++i) {
        float4 v = s4[i];
        __nv_bfloat16 h0,h1,h2,h3,l0,l1,l2,l3;
        split2(v.x * scale, h0, l0); split2(v.y * scale, h1, l1);
        split2(v.z * scale, h2, l2); split2(v.w * scale, h3, l3);
        uint32_t ph0 = (uint32_t)__bfloat16_as_ushort(h0) | ((uint32_t)__bfloat16_as_ushort(h1) << 16);
        uint32_t ph1 = (uint32_t)__bfloat16_as_ushort(h2) | ((uint32_t)__bfloat16_as_ushort(h3) << 16);
        uint32_t pl0 = (uint32_t)__bfloat16_as_ushort(l0) | ((uint32_t)__bfloat16_as_ushort(l1) << 16);
        uint32_t pl1 = (uint32_t)__bfloat16_as_ushort(l2) | ((uint32_t)__bfloat16_as_ushort(l3) << 16);
        int off = row * AT_STRIDE + c0 + i * 4;
        *(uint2*)(hi + off) = make_uint2(ph0, ph1);
        *(uint2*)(lo + off) = make_uint2(pl0, pl1);
    }
}

__device__ __forceinline__ void packsplit(float f0, float f1, uint32_t& ph, uint32_t& pl) {
    __nv_bfloat16 h0, l0, h1, l1;
    split2(f0, h0, l0); split2(f1, h1, l1);
    ph = (uint32_t)__bfloat16_as_ushort(h0) | ((uint32_t)__bfloat16_as_ushort(h1) << 16);
    pl = (uint32_t)__bfloat16_as_ushort(l0) | ((uint32_t)__bfloat16_as_ushort(l1) << 16);
}

__global__ void __launch_bounds__(128)
attn_mma_kernel(const float* __restrict__ qkv,
                __nv_bfloat16* __restrict__ z_hi, __nv_bfloat16* __restrict__ z_lo) {
    __shared__ __nv_bfloat16 sKh[64 * AT_STRIDE], sKl[64 * AT_STRIDE];
    __shared__ __nv_bfloat16 sVh[64 * AT_STRIDE], sVl[64 * AT_STRIDE];

    const int tid  = threadIdx.x;
    const int wid  = tid >> 5;
    const int lane = tid & 31;
    const int qt = (int)gridDim.x - 1 - (int)blockIdx.x;   // longest-work CTAs first
    const int bh = blockIdx.y;
    const int b = bh >> 4, h = bh & 15;

    const float* qp = qkv + (size_t)b * S_ * 3072 + h * 64;
    const float* kp = qp + 1024;
    const float* vp = qp + 2048;

    uint32_t aKh = smem_u32(sKh), aKl = smem_u32(sKl);
    uint32_t aVh = smem_u32(sVh), aVl = smem_u32(sVl);

    // Stage Q (scaled by 1/8) through K smem, build A-fragments, then release smem.
    at_fill64(qp + (size_t)(qt * 64) * 3072, sKh, sKl, tid, 0.125f);
    __syncthreads();
    uint32_t Qh[4][4], Ql[4][4];
    {
        int arow = wid * 16 + (lane & 15);
        #pragma unroll
        for (int ks = 0; ks < 4; ++ks) {
            uint32_t off = (uint32_t)(arow * AT_STRIDE + ks * 16 + ((lane >> 4) << 3)) * 2;
            ldsm4(Qh[ks], aKh + off);
            ldsm4(Ql[ks], aKl + off);
        }
    }
    __syncthreads();

    float m0 = -1e30f, m1 = -1e30f, l0 = 0.f, l1 = 0.f;
    float acc[8][4];
    #pragma unroll
    for (int nt = 0; nt < 8; ++nt)
        #pragma unroll
        for (int q = 0; q < 4; ++q) acc[nt][q] = 0.f;

    const int myrow = wid * 16 + (lane >> 2);   // row within 64-tile (also +8)
    const int mycol = (lane & 3) * 2;           // col pair base within 8-tile

    for (int jt = 0; jt <= qt; ++jt) {
        at_fill64(kp + (size_t)(jt * 64) * 3072, sKh, sKl, tid, 1.0f);
        at_fill64(vp + (size_t)(jt * 64) * 3072, sVh, sVl, tid, 1.0f);
        __syncthreads();

        // ---- S = Q @ K^T (scaled), 3 split products ----
        float s[8][4];
        #pragma unroll
        for (int nt = 0; nt < 8; ++nt)
            #pragma unroll
            for (int q = 0; q < 4; ++q) s[nt][q] = 0.f;

        {
            const int quad = lane >> 3;
            #pragma unroll
            for (int np = 0; np < 4; ++np) {
                int brow = np * 16 + ((quad >> 1) << 3) + (lane & 7);
                #pragma unroll
                for (int ks = 0; ks < 4; ++ks) {
                    uint32_t boff = (uint32_t)(brow * AT_STRIDE + ks * 16 + ((quad & 1) << 3)) * 2;
                    uint32_t Bh[4], Bl[4];
                    ldsm4(Bh, aKh + boff);
                    ldsm4(Bl, aKl + boff);
                    mma16816(s[2*np],   Qh[ks], Bh[0], Bh[1]);
                    mma16816(s[2*np],   Qh[ks], Bl[0], Bl[1]);
                    mma16816(s[2*np],   Ql[ks], Bh[0], Bh[1]);
                    mma16816(s[2*np+1], Qh[ks], Bh[2], Bh[3]);
                    mma16816(s[2*np+1], Qh[ks], Bl[2], Bl[3]);
                    mma16816(s[2*np+1], Ql[ks], Bh[2], Bh[3]);
                }
            }
        }

        // ---- causal mask on the diagonal tile ----
        if (jt == qt) {
            #pragma unroll
            for (int nt = 0; nt < 8; ++nt) {
                int col0 = nt * 8 + mycol;
                if (col0     > myrow)     s[nt][0] = IGNOREV;
                if (col0 + 1 > myrow)     s[nt][1] = IGNOREV;
                if (col0     > myrow + 8) s[nt][2] = IGNOREV;
                if (col0 + 1 > myrow + 8) s[nt][3] = IGNOREV;
            }
        }

        // ---- online softmax (per-lane two rows; quad reduce) ----
        float mx0 = -1e30f, mx1 = -1e30f;
        #pragma unroll
        for (int nt = 0; nt < 8; ++nt) {
            mx0 = fmaxf(mx0, fmaxf(s[nt][0], s[nt][1]));
            mx1 = fmaxf(mx1, fmaxf(s[nt][2], s[nt][3]));
        }
        #pragma unroll
        for (int o = 1; o < 4; o <<= 1) {
            mx0 = fmaxf(mx0, __shfl_xor_sync(0xffffffffu, mx0, o));
            mx1 = fmaxf(mx1, __shfl_xor_sync(0xffffffffu, mx1, o));
        }
        float nm0 = fmaxf(m0, mx0), nm1 = fmaxf(m1, mx1);
        float al0 = __expf(m0 - nm0), al1 = __expf(m1 - nm1);
        float rs0 = 0.f, rs1 = 0.f;
        #pragma unroll
        for (int nt = 0; nt < 8; ++nt) {
            s[nt][0] = __expf(s[nt][0] - nm0); rs0 += s[nt][0];
            s[nt][1] = __expf(s[nt][1] - nm0); rs0 += s[nt][1];
            s[nt][2] = __expf(s[nt][2] - nm1); rs1 += s[nt][2];
            s[nt][3] = __expf(s[nt][3] - nm1); rs1 += s[nt][3];
        }
        #pragma unroll
        for (int o = 1; o < 4; o <<= 1) {
            rs0 += __shfl_xor_sync(0xffffffffu, rs0, o);
            rs1 += __shfl_xor_sync(0xffffffffu, rs1, o);
        }
        l0 = l0 * al0 + rs0; l1 = l1 * al1 + rs1;
        m0 = nm0; m1 = nm1;
        #pragma unroll
        for (int nt = 0; nt < 8; ++nt) {
            acc[nt][0] *= al0; acc[nt][1] *= al0;
            acc[nt][2] *= al1; acc[nt][3] *= al1;
        }

        // ---- O += P @ V (P hi/lo from regs; V hi/lo via ldmatrix.trans) ----
        #pragma unroll
        for (int kt = 0; kt < 4; ++kt) {
            uint32_t Ph[4], Pl[4];
            packsplit(s[2*kt][0],   s[2*kt][1],   Ph[0], Pl[0]);
            packsplit(s[2*kt][2],   s[2*kt][3],   Ph[1], Pl[1]);
            packsplit(s[2*kt+1][0], s[2*kt+1][1], Ph[2], Pl[2]);
            packsplit(s[2*kt+1][2], s[2*kt+1][3], Ph[3], Pl[3]);
            int vrow = kt * 16 + (lane & 15);
            #pragma unroll
            for (int nd = 0; nd < 4; ++nd) {
                uint32_t voff = (uint32_t)(vrow * AT_STRIDE + nd * 16 + ((lane >> 4) << 3)) * 2;
                uint32_t Vhf[4], Vlf[4];
                ldsm4t(Vhf, aVh + voff);
                ldsm4t(Vlf, aVl + voff);
                mma16816(acc[2*nd],   Ph, Vhf[0], Vhf[1]);
                mma16816(acc[2*nd],   Ph, Vlf[0], Vlf[1]);
                mma16816(acc[2*nd],   Pl, Vhf[0], Vhf[1]);
                mma16816(acc[2*nd+1], Ph, Vhf[2], Vhf[3]);
                mma16816(acc[2*nd+1], Ph, Vlf[2], Vlf[3]);
                mma16816(acc[2*nd+1], Pl, Vhf[2], Vhf[3]);
            }
        }
        __syncthreads();
    }

    // ---- epilogue: z[b, row, h, dh] as bf16 hi/lo ----
    float inv0 = 1.f / l0, inv1 = 1.f / l1;
    int rowA = qt * 64 + myrow;
    #pragma unroll
    for (int nt = 0; nt < 8; ++nt) {
        int col = h * 64 + nt * 8 + mycol;
        size_t offA = ((size_t)b * S_ + rowA) * D_ + col;
        size_t offB = ((size_t)b * S_ + rowA + 8) * D_ + col;
        uint32_t ph, pl;
        packsplit(acc[nt][0] * inv0, acc[nt][1] * inv0, ph, pl);
        *(uint32_t*)(z_hi + offA) = ph;
        *(uint32_t*)(z_lo + offA) = pl;
        packsplit(acc[nt][2] * inv1, acc[nt][3] * inv1, ph, pl);
        *(uint32_t*)(z_hi + offB) = ph;
        *(uint32_t*)(z_lo + offB) = pl;
    }
}

// ---------------- Host launch ----------------
template <typename Tp>
static Tp* sym_addr(const void* sym) {
    void* p = nullptr;
    cudaGetSymbolAddress(&p, sym);
    return (Tp*)p;
}

extern "C" void kernel_launch(void* const* d_in, const int* in_sizes, int n_in,
                              void* d_out, int out_size) {
    const float* x     = (const float*)d_in[0];
    const float* W_Q   = (const float*)d_in[1];
    const float* W_K   = (const float*)d_in[2];
    const float* W_V   = (const float*)d_in[3];
    const float* W_O   = (const float*)d_in[4];
    const float* b_Q   = (const float*)d_in[5];
    const float* b_K   = (const float*)d_in[6];
    const float* b_V   = (const float*)d_in[7];
    const float* b_O   = (const float*)d_in[8];
    const float* W_in  = (const float*)d_in[9];
    const float* b_in  = (const float*)d_in[10];
    const float* W_out = (const float*)d_in[11];
    const float* b_out = (const float*)d_in[12];
    float* out = (float*)d_out;

    __nv_bfloat16* xn_hi  = sym_addr<__nv_bfloat16>(g_xn_hi);
    __nv_bfloat16* xn_lo  = sym_addr<__nv_bfloat16>(g_xn_lo);
    float*         qkv    = sym_addr<float>(g_qkv);
    __nv_bfloat16* z_hi   = sym_addr<__nv_bfloat16>(g_z_hi);
    __nv_bfloat16* z_lo   = sym_addr<__nv_bfloat16>(g_z_lo);
    float*         rmid   = sym_addr<float>(g_rmid);
    __nv_bfloat16* m_hi   = sym_addr<__nv_bfloat16>(g_m_hi);
    __nv_bfloat16* m_lo   = sym_addr<__nv_bfloat16>(g_m_lo);
    __nv_bfloat16* hid_hi = sym_addr<__nv_bfloat16>(g_hid_hi);
    __nv_bfloat16* hid_lo = sym_addr<__nv_bfloat16>(g_hid_lo);
    __nv_bfloat16* Wqkv_hi = sym_addr<__nv_bfloat16>(g_Wqkv_hi);
    __nv_bfloat16* Wqkv_lo = sym_addr<__nv_bfloat16>(g_Wqkv_lo);
    __nv_bfloat16* Wo_hi   = sym_addr<__nv_bfloat16>(g_Wo_hi);
    __nv_bfloat16* Wo_lo   = sym_addr<__nv_bfloat16>(g_Wo_lo);
    __nv_bfloat16* Win_hi  = sym_addr<__nv_bfloat16>(g_Win_hi);
    __nv_bfloat16* Win_lo  = sym_addr<__nv_bfloat16>(g_Win_lo);
    __nv_bfloat16* Wout_hi = sym_addr<__nv_bfloat16>(g_Wout_hi);
    __nv_bfloat16* Wout_lo = sym_addr<__nv_bfloat16>(g_Wout_lo);
    float*         bqkv    = sym_addr<float>(g_bqkv);

    cudaFuncSetAttribute(gemm_mma<0,0,0>, cudaFuncAttributeMaxDynamicSharedMemorySize, GEMM_SMEM);
    cudaFuncSetAttribute(gemm_mma<0,1,0>, cudaFuncAttributeMaxDynamicSharedMemorySize, GEMM_SMEM);
    cudaFuncSetAttribute(gemm_mma<1,0,1>, cudaFuncAttributeMaxDynamicSharedMemorySize, GEMM_SMEM);

    // Weight splits
    const int NW1 = (D_ * D_) / 4;
    split_kernel<<<(NW1 + 255) / 256, 256>>>(W_Q, Wqkv_hi,               Wqkv_lo,               NW1);
    split_kernel<<<(NW1 + 255) / 256, 256>>>(W_K, Wqkv_hi + D_ * D_,     Wqkv_lo + D_ * D_,     NW1);
    split_kernel<<<(NW1 + 255) / 256, 256>>>(W_V, Wqkv_hi + 2 * D_ * D_, Wqkv_lo + 2 * D_ * D_, NW1);
    wo_split_kernel<<<(D_ * D_) / 256, 256>>>(W_O, Wo_hi, Wo_lo);
    const int NW2 = (DM_ * D_) / 4;
    split_kernel<<<(NW2 + 255) / 256, 256>>>(W_in,  Win_hi,  Win_lo,  NW2);
    split_kernel<<<(NW2 + 255) / 256, 256>>>(W_out, Wout_hi, Wout_lo, NW2);
    bias_concat_kernel<<<12, 256>>>(b_Q, b_K, b_V, bqkv);

    // LN1 -> xn hi/lo
    ln_split_kernel<<<T_, 256>>>(x, xn_hi, xn_lo);

    // Fused QKV projection: qkv[T,3072]
    gemm_mma<0,0,0><<<dim3(3072 / 128, T_ / 128), 256, GEMM_SMEM>>>(
        T_, 3072, D_, xn_hi, xn_lo, Wqkv_hi, Wqkv_lo, bqkv, nullptr, qkv, nullptr, nullptr);

    // Tensor-core attention -> z hi/lo
    attn_mma_kernel<<<dim3(S_ / 64, B_ * H_), 128>>>(qkv, z_hi, z_lo);

    // O projection + residual: rmid = x + z @ Wo^T + b_O
    gemm_mma<0,1,0><<<dim3(D_ / 128, T_ / 128), 256, GEMM_SMEM>>>(
        T_, D_, D_, z_hi, z_lo, Wo_hi, Wo_lo, b_O, x, rmid, nullptr, nullptr);

    // LN2 -> m hi/lo
    ln_split_kernel<<<T_, 256>>>(rmid, m_hi, m_lo);

    // MLP in + gelu -> hid hi/lo (bf16 split output)
    gemm_mma<1,0,1><<<dim3(DM_ / 128, T_ / 128), 256, GEMM_SMEM>>>(
        T_, DM_, D_, m_hi, m_lo, Win_hi, Win_lo, b_in, nullptr, nullptr, hid_hi, hid_lo);

    // MLP out + residual -> final output
    gemm_mma<0,1,0><<<dim3(D_ / 128, T_ / 128), 256, GEMM_SMEM>>>(
        T_, D_, DM_, hid_hi, hid_lo, Wout_hi, Wout_lo, b_out, rmid, out, nullptr, nullptr);
}

// round 15
// speedup vs baseline: 1.9131x; 1.0837x over previous
#include <cuda_runtime.h>
#include <cuda_bf16.h>
#include <math.h>
#include <stdint.h>

// ---------------- Problem dims ----------------
#define B_      2
#define S_      2048
#define T_      4096          // B*S tokens
#define D_      1024
#define H_      16
#define DH_     64
#define DM_     4096
#define EPSV    1e-5f
#define IGNOREV -100000.0f

// ---------------- Small helpers ----------------
__device__ __forceinline__ uint32_t smem_u32(const void* p) {
    uint32_t a;
    asm("{ .reg .u64 t; cvta.to.shared.u64 t, %1; cvt.u32.u64 %0, t; }" : "=r"(a) : "l"(p));
    return a;
}
__device__ __forceinline__ void split2(float v, __nv_bfloat16& h, __nv_bfloat16& l) {
    h = __float2bfloat16(v);
    l = __float2bfloat16(v - __bfloat162float(h));
}
__device__ __forceinline__ float gelu_new_f(float x) {
    float x3 = x * x * x;
    return 0.5f * x * (1.0f + tanhf(0.7978845608028654f * (x + 0.044715f * x3)));
}

// ---------------- Baseline-PTX tensor-core primitives (sm_80+; valid on sm_103) ----
__device__ __forceinline__ void cp16(uint32_t saddr, const void* g) {
    asm volatile("cp.async.cg.shared.global [%0], [%1], 16;" :: "r"(saddr), "l"(g));
}
__device__ __forceinline__ void cp_commit() {
    asm volatile("cp.async.commit_group;" ::: "memory");
}
template <int N>
__device__ __forceinline__ void cp_wait() {
    asm volatile("cp.async.wait_group %0;" :: "n"(N) : "memory");
}
__device__ __forceinline__ void ldsm4(uint32_t (&r)[4], uint32_t a) {
    asm volatile("ldmatrix.sync.aligned.m8n8.x4.shared.b16 {%0,%1,%2,%3}, [%4];"
                 : "=r"(r[0]), "=r"(r[1]), "=r"(r[2]), "=r"(r[3]) : "r"(a));
}
__device__ __forceinline__ void ldsm4t(uint32_t (&r)[4], uint32_t a) {
    asm volatile("ldmatrix.sync.aligned.m8n8.x4.trans.shared.b16 {%0,%1,%2,%3}, [%4];"
                 : "=r"(r[0]), "=r"(r[1]), "=r"(r[2]), "=r"(r[3]) : "r"(a));
}
__device__ __forceinline__ void mma16816(float (&c)[4], const uint32_t (&a)[4],
                                         uint32_t b0, uint32_t b1) {
    asm volatile(
        "mma.sync.aligned.m16n8k16.row.col.f32.bf16.bf16.f32 "
        "{%0,%1,%2,%3}, {%4,%5,%6,%7}, {%8,%9}, {%0,%1,%2,%3};"
        : "+f"(c[0]), "+f"(c[1]), "+f"(c[2]), "+f"(c[3])
        : "r"(a[0]), "r"(a[1]), "r"(a[2]), "r"(a[3]), "r"(b0), "r"(b1));
}

// ---------------- Scratch (static device globals; no allocation) ----------------
__device__ __nv_bfloat16 g_xn_hi [T_ * D_];
__device__ __nv_bfloat16 g_xn_lo [T_ * D_];
__device__ float         g_qkv   [(size_t)T_ * 3072];
__device__ __nv_bfloat16 g_z_hi  [T_ * D_];
__device__ __nv_bfloat16 g_z_lo  [T_ * D_];
__device__ float         g_rmid  [T_ * D_];
__device__ __nv_bfloat16 g_m_hi  [T_ * D_];
__device__ __nv_bfloat16 g_m_lo  [T_ * D_];
__device__ __nv_bfloat16 g_hid_hi[(size_t)T_ * DM_];
__device__ __nv_bfloat16 g_hid_lo[(size_t)T_ * DM_];
__device__ __nv_bfloat16 g_Wqkv_hi[3 * D_ * D_];
__device__ __nv_bfloat16 g_Wqkv_lo[3 * D_ * D_];
__device__ __nv_bfloat16 g_Wo_hi [D_ * D_];
__device__ __nv_bfloat16 g_Wo_lo [D_ * D_];
__device__ __nv_bfloat16 g_Win_hi[(size_t)DM_ * D_];
__device__ __nv_bfloat16 g_Win_lo[(size_t)DM_ * D_];
__device__ __nv_bfloat16 g_Wout_hi[(size_t)D_ * DM_];
__device__ __nv_bfloat16 g_Wout_lo[(size_t)D_ * DM_];
__device__ float         g_bqkv  [3072];

// ---------------- Fused weight split (all straight [N,K] weights + bias concat) ----
__device__ __forceinline__ void split4_store(float4 v,
                                             __nv_bfloat16* __restrict__ hi,
                                             __nv_bfloat16* __restrict__ lo, int i) {
    __nv_bfloat16 h0,h1,h2,h3,l0,l1,l2,l3;
    split2(v.x,h0,l0); split2(v.y,h1,l1); split2(v.z,h2,l2); split2(v.w,h3,l3);
    uint32_t ph0 = (uint32_t)__bfloat16_as_ushort(h0) | ((uint32_t)__bfloat16_as_ushort(h1) << 16);
    uint32_t ph1 = (uint32_t)__bfloat16_as_ushort(h2) | ((uint32_t)__bfloat16_as_ushort(h3) << 16);
    uint32_t pl0 = (uint32_t)__bfloat16_as_ushort(l0) | ((uint32_t)__bfloat16_as_ushort(l1) << 16);
    uint32_t pl1 = (uint32_t)__bfloat16_as_ushort(l2) | ((uint32_t)__bfloat16_as_ushort(l3) << 16);
    ((uint2*)hi)[i] = make_uint2(ph0, ph1);
    ((uint2*)lo)[i] = make_uint2(pl0, pl1);
}

#define N4_QKV1 (D_ * D_ / 4)          // 262144 float4 per QKV weight
#define N4_MLP  (DM_ * D_ / 4)         // 1048576 float4 per MLP weight
#define N4_ALL  (3 * N4_QKV1 + 2 * N4_MLP)   // 2883584

__global__ void split_all_kernel(const float* __restrict__ WQ, const float* __restrict__ WK,
                                 const float* __restrict__ WV, const float* __restrict__ Win,
                                 const float* __restrict__ Wout,
                                 __nv_bfloat16* __restrict__ Wqkv_hi, __nv_bfloat16* __restrict__ Wqkv_lo,
                                 __nv_bfloat16* __restrict__ Win_hi,  __nv_bfloat16* __restrict__ Win_lo,
                                 __nv_bfloat16* __restrict__ Wout_hi, __nv_bfloat16* __restrict__ Wout_lo,
                                 const float* __restrict__ bq, const float* __restrict__ bk,
                                 const float* __restrict__ bv, float* __restrict__ bqkv) {
    int i = blockIdx.x * 256 + threadIdx.x;
    if (i < N4_ALL) {
        if (i < 3 * N4_QKV1) {
            int seg = i / N4_QKV1, j = i - seg * N4_QKV1;
            const float* src = (seg == 0) ? WQ : (seg == 1) ? WK : WV;
            split4_store(((const float4*)src)[j],
                         Wqkv_hi + (size_t)seg * D_ * D_, Wqkv_lo + (size_t)seg * D_ * D_, j);
        } else if (i < 3 * N4_QKV1 + N4_MLP) {
            int j = i - 3 * N4_QKV1;
            split4_store(((const float4*)Win)[j], Win_hi, Win_lo, j);
        } else {
            int j = i - 3 * N4_QKV1 - N4_MLP;
            split4_store(((const float4*)Wout)[j], Wout_hi, Wout_lo, j);
        }
    } else {
        int j = i - N4_ALL;
        if (j < 3072) {
            float v = (j < 1024) ? bq[j] : (j < 2048) ? bk[j - 1024] : bv[j - 2048];
            bqkv[j] = v;
        }
    }
}

// W_O [H, D, DH] -> [N=d][K=h*64+dh] bf16 hi/lo (gather pattern, separate kernel)
__global__ void wo_split_kernel(const float* __restrict__ wo,
                                __nv_bfloat16* __restrict__ hi,
                                __nv_bfloat16* __restrict__ lo) {
    int idx = blockIdx.x * 256 + threadIdx.x;        // 1M elems
    int d  = idx >> 10;
    int kk = idx & 1023;
    int h  = kk >> 6, dh = kk & 63;
    float v = wo[(size_t)h * D_ * DH_ + (size_t)d * DH_ + dh];
    __nv_bfloat16 hh, ll; split2(v, hh, ll);
    hi[idx] = hh; lo[idx] = ll;
}

// ---------------- LayerNorm -> bf16 hi/lo ----------------
__global__ void ln_split_kernel(const float* __restrict__ src,
                                __nv_bfloat16* __restrict__ hi,
                                __nv_bfloat16* __restrict__ lo) {
    int row = blockIdx.x;
    float4 vv = ((const float4*)(src + (size_t)row * D_))[threadIdx.x];
    float s  = vv.x + vv.y + vv.z + vv.w;
    float s2 = vv.x*vv.x + vv.y*vv.y + vv.z*vv.z + vv.w*vv.w;
    #pragma unroll
    for (int o = 16; o > 0; o >>= 1) {
        s  += __shfl_xor_sync(0xffffffffu, s,  o);
        s2 += __shfl_xor_sync(0xffffffffu, s2, o);
    }
    __shared__ float ws[8], ws2[8];
    __shared__ float s_mean, s_r;
    int w = threadIdx.x >> 5;
    if ((threadIdx.x & 31) == 0) { ws[w] = s; ws2[w] = s2; }
    __syncthreads();
    if (threadIdx.x == 0) {
        float a = 0.f, b2 = 0.f;
        #pragma unroll
        for (int i = 0; i < 8; i++) { a += ws[i]; b2 += ws2[i]; }
        float mean = a * (1.f / D_);
        float var  = b2 * (1.f / D_) - mean * mean;
        s_mean = mean; s_r = rsqrtf(var + EPSV);
    }
    __syncthreads();
    float mean = s_mean, r = s_r;
    float o0 = (vv.x - mean) * r, o1 = (vv.y - mean) * r;
    float o2 = (vv.z - mean) * r, o3 = (vv.w - mean) * r;
    __nv_bfloat16 h0,h1,h2,h3,l0,l1,l2,l3;
    split2(o0,h0,l0); split2(o1,h1,l1); split2(o2,h2,l2); split2(o3,h3,l3);
    uint32_t ph0 = (uint32_t)__bfloat16_as_ushort(h0) | ((uint32_t)__bfloat16_as_ushort(h1) << 16);
    uint32_t ph1 = (uint32_t)__bfloat16_as_ushort(h2) | ((uint32_t)__bfloat16_as_ushort(h3) << 16);
    uint32_t pl0 = (uint32_t)__bfloat16_as_ushort(l0) | ((uint32_t)__bfloat16_as_ushort(l1) << 16);
    uint32_t pl1 = (uint32_t)__bfloat16_as_ushort(l2) | ((uint32_t)__bfloat16_as_ushort(l3) << 16);
    size_t base = (size_t)row * D_ + threadIdx.x * 4;
    ((uint2*)(hi + base))[0] = make_uint2(ph0, ph1);
    ((uint2*)(lo + base))[0] = make_uint2(pl0, pl1);
}

// ================= mma.sync bf16-split GEMM — 4-stage cp.async pipeline ===========
#define GSM_STRIDE 40
#define GSM_ARR_B  (128 * GSM_STRIDE * 2)     // 10240 B
#define GSM_STAGE_B (4 * GSM_ARR_B)           // 40960 B
#define GEMM_NSTG  4
#define GEMM_SMEM  (GEMM_NSTG * GSM_STAGE_B)  // 163840 B

__device__ __forceinline__ void fill_stage(
    uint32_t sbase,
    const __nv_bfloat16* __restrict__ Ahi, const __nv_bfloat16* __restrict__ Alo,
    const __nv_bfloat16* __restrict__ Bhi, const __nv_bfloat16* __restrict__ Blo,
    int m0, int n0, int kb, int K, int tid) {
    int row = tid & 127;
    int kc0 = tid >> 7;
    #pragma unroll
    for (int i = 0; i < 2; ++i) {
        int kc = kc0 + i * 2;
        uint32_t soff = (uint32_t)(row * GSM_STRIDE + kc * 8) * 2;
        size_t ga = (size_t)(m0 + row) * K + kb + kc * 8;
        size_t gb = (size_t)(n0 + row) * K + kb + kc * 8;
        cp16(sbase +                 soff, Ahi + ga);
        cp16(sbase + GSM_ARR_B +     soff, Alo + ga);
        cp16(sbase + 2 * GSM_ARR_B + soff, Bhi + gb);
        cp16(sbase + 3 * GSM_ARR_B + soff, Blo + gb);
    }
}

template <int ACT, int RES, int OUTBF16>
__global__ void __launch_bounds__(256, 1)
gemm_mma(int M, int N, int K,
         const __nv_bfloat16* __restrict__ Ahi, const __nv_bfloat16* __restrict__ Alo,
         const __nv_bfloat16* __restrict__ Bhi, const __nv_bfloat16* __restrict__ Blo,
         const float* __restrict__ bias, const float* __restrict__ resid,
         float* __restrict__ Cf,
         __nv_bfloat16* __restrict__ Chi, __nv_bfloat16* __restrict__ Clo) {
    extern __shared__ char sm_raw[];
    uint32_t sb = smem_u32(sm_raw);
    const int tid  = threadIdx.x;
    const int wid  = tid >> 5;
    const int lane = tid & 31;
    const int m0 = blockIdx.y * 128;
    const int n0 = blockIdx.x * 128;
    const int wr0 = (wid >> 1) * 32;
    const int wc0 = (wid & 1) * 64;

    float acc[2][8][4];
    #pragma unroll
    for (int mt = 0; mt < 2; ++mt)
        #pragma unroll
        for (int j = 0; j < 8; ++j)
            #pragma unroll
            for (int q = 0; q < 4; ++q) acc[mt][j][q] = 0.f;

    const int nst = K >> 5;

    // Prefill 3 stages (one commit group each)
    fill_stage(sb,                   Ahi, Alo, Bhi, Blo, m0, n0, 0,       K, tid); cp_commit();
    fill_stage(sb + GSM_STAGE_B,     Ahi, Alo, Bhi, Blo, m0, n0, 1 << 5,  K, tid); cp_commit();
    fill_stage(sb + 2 * GSM_STAGE_B, Ahi, Alo, Bhi, Blo, m0, n0, 2 << 5,  K, tid); cp_commit();

    for (int c = 0; c < nst; ++c) {
        cp_wait<2>();            // retires stage c's group (always-commit accounting)
        __syncthreads();         // stage c visible; stage c-1 free for refill

        // Prefetch stage c+3 into the buffer freed at this barrier.
        if (c + 3 < nst)
            fill_stage(sb + (uint32_t)((c + 3) & 3) * GSM_STAGE_B,
                       Ahi, Alo, Bhi, Blo, m0, n0, (c + 3) << 5, K, tid);
        cp_commit();             // commit every iteration (empty groups keep FIFO exact)

        uint32_t st = sb + (uint32_t)(c & 3) * GSM_STAGE_B;
        #pragma unroll
        for (int ks = 0; ks < 2; ++ks) {
            const int k0 = ks * 16;
            uint32_t Ah[2][4], Al[2][4];
            #pragma unroll
            for (int mt = 0; mt < 2; ++mt) {
                int arow = wr0 + mt * 16 + (lane & 15);
                uint32_t aoff = (uint32_t)(arow * GSM_STRIDE + k0 + ((lane >> 4) << 3)) * 2;
                ldsm4(Ah[mt], st + aoff);
                ldsm4(Al[mt], st + GSM_ARR_B + aoff);
            }
            uint32_t Bh[4][4], Bl[4][4];
            #pragma unroll
            for (int np = 0; np < 4; ++np) {
                int quad = lane >> 3;
                int brow = wc0 + np * 16 + ((quad >> 1) << 3) + (lane & 7);
                uint32_t boff = (uint32_t)(brow * GSM_STRIDE + k0 + ((quad & 1) << 3)) * 2;
                ldsm4(Bh[np], st + 2 * GSM_ARR_B + boff);
                ldsm4(Bl[np], st + 3 * GSM_ARR_B + boff);
            }
            #pragma unroll
            for (int mt = 0; mt < 2; ++mt)
                #pragma unroll
                for (int j = 0; j < 8; ++j) {
                    const int np = j >> 1;
                    const int hreg = (j & 1) << 1;
                    mma16816(acc[mt][j], Ah[mt], Bh[np][hreg], Bh[np][hreg + 1]);
                    mma16816(acc[mt][j], Ah[mt], Bl[np][hreg], Bl[np][hreg + 1]);
                    mma16816(acc[mt][j], Al[mt], Bh[np][hreg], Bh[np][hreg + 1]);
                }
        }
    }

    const int qrow = lane >> 2;
    const int qcol = (lane & 3) * 2;
    #pragma unroll
    for (int mt = 0; mt < 2; ++mt)
        #pragma unroll
        for (int j = 0; j < 8; ++j)
            #pragma unroll
            for (int half = 0; half < 2; ++half) {
                int row = m0 + wr0 + mt * 16 + qrow + half * 8;
                int col = n0 + wc0 + j * 8 + qcol;
                float v0 = acc[mt][j][half * 2 + 0] + bias[col];
                float v1 = acc[mt][j][half * 2 + 1] + bias[col + 1];
                if (ACT) { v0 = gelu_new_f(v0); v1 = gelu_new_f(v1); }
                size_t off = (size_t)row * N + col;
                if (RES) {
                    float2 rr = *(const float2*)(resid + off);
                    v0 += rr.x; v1 += rr.y;
                }
                if (!OUTBF16) {
                    *(float2*)(Cf + off) = make_float2(v0, v1);
                } else {
                    __nv_bfloat16 h0, h1, l0, l1;
                    split2(v0, h0, l0);
                    split2(v1, h1, l1);
                    uint32_t ph = (uint32_t)__bfloat16_as_ushort(h0) |
                                  ((uint32_t)__bfloat16_as_ushort(h1) << 16);
                    uint32_t pl = (uint32_t)__bfloat16_as_ushort(l0) |
                                  ((uint32_t)__bfloat16_as_ushort(l1) << 16);
                    *(uint32_t*)(Chi + off) = ph;
                    *(uint32_t*)(Clo + off) = pl;
                }
            }
}

// ================= Tensor-core causal flash attention (unchanged, verified) =======
#define AT_STRIDE 72

__device__ __forceinline__ void at_fill64(const float* __restrict__ src,
                                          __nv_bfloat16* __restrict__ hi,
                                          __nv_bfloat16* __restrict__ lo,
                                          int tid, float scale) {
    int row = tid >> 1;
    int c0  = (tid & 1) * 32;
    const float4* s4 = (const float4*)(src + (size_t)row * 3072 + c0);
    #pragma unroll
    for (int i = 0; i < 8; ++i) {
        float4 v = s4[i];
        __nv_bfloat16 h0,h1,h2,h3,l0,l1,l2,l3;
        split2(v.x * scale, h0, l0); split2(v.y * scale, h1, l1);
        split2(v.z * scale, h2, l2); split2(v.w * scale, h3, l3);
        uint32_t ph0 = (uint32_t)__bfloat16_as_ushort(h0) | ((uint32_t)__bfloat16_as_ushort(h1) << 16);
        uint32_t ph1 = (uint32_t)__bfloat16_as_ushort(h2) | ((uint32_t)__bfloat16_as_ushort(h3) << 16);
        uint32_t pl0 = (uint32_t)__bfloat16_as_ushort(l0) | ((uint32_t)__bfloat16_as_ushort(l1) << 16);
        uint32_t pl1 = (uint32_t)__bfloat16_as_ushort(l2) | ((uint32_t)__bfloat16_as_ushort(l3) << 16);
        int off = row * AT_STRIDE + c0 + i * 4;
        *(uint2*)(hi + off) = make_uint2(ph0, ph1);
        *(uint2*)(lo + off) = make_uint2(pl0, pl1);
    }
}

__device__ __forceinline__ void packsplit(float f0, float f1, uint32_t& ph, uint32_t& pl) {
    __nv_bfloat16 h0, l0, h1, l1;
    split2(f0, h0, l0); split2(f1, h1, l1);
    ph = (uint32_t)__bfloat16_as_ushort(h0) | ((uint32_t)__bfloat16_as_ushort(h1) << 16);
    pl = (uint32_t)__bfloat16_as_ushort(l0) | ((uint32_t)__bfloat16_as_ushort(l1) << 16);
}

__global__ void __launch_bounds__(128)
attn_mma_kernel(const float* __restrict__ qkv,
                __nv_bfloat16* __restrict__ z_hi, __nv_bfloat16* __restrict__ z_lo) {
    __shared__ __nv_bfloat16 sKh[64 * AT_STRIDE], sKl[64 * AT_STRIDE];
    __shared__ __nv_bfloat16 sVh[64 * AT_STRIDE], sVl[64 * AT_STRIDE];

    const int tid  = threadIdx.x;
    const int wid  = tid >> 5;
    const int lane = tid & 31;
    const int qt = (int)gridDim.x - 1 - (int)blockIdx.x;
    const int bh = blockIdx.y;
    const int b = bh >> 4, h = bh & 15;

    const float* qp = qkv + (size_t)b * S_ * 3072 + h * 64;
    const float* kp = qp + 1024;
    const float* vp = qp + 2048;

    uint32_t aKh = smem_u32(sKh), aKl = smem_u32(sKl);
    uint32_t aVh = smem_u32(sVh), aVl = smem_u32(sVl);

    at_fill64(qp + (size_t)(qt * 64) * 3072, sKh, sKl, tid, 0.125f);
    __syncthreads();
    uint32_t Qh[4][4], Ql[4][4];
    {
        int arow = wid * 16 + (lane & 15);
        #pragma unroll
        for (int ks = 0; ks < 4; ++ks) {
            uint32_t off = (uint32_t)(arow * AT_STRIDE + ks * 16 + ((lane >> 4) << 3)) * 2;
            ldsm4(Qh[ks], aKh + off);
            ldsm4(Ql[ks], aKl + off);
        }
    }
    __syncthreads();

    float m0 = -1e30f, m1 = -1e30f, l0 = 0.f, l1 = 0.f;
    float acc[8][4];
    #pragma unroll
    for (int nt = 0; nt < 8; ++nt)
        #pragma unroll
        for (int q = 0; q < 4; ++q) acc[nt][q] = 0.f;

    const int myrow = wid * 16 + (lane >> 2);
    const int mycol = (lane & 3) * 2;

    for (int jt = 0; jt <= qt; ++jt) {
        at_fill64(kp + (size_t)(jt * 64) * 3072, sKh, sKl, tid, 1.0f);
        at_fill64(vp + (size_t)(jt * 64) * 3072, sVh, sVl, tid, 1.0f);
        __syncthreads();

        float s[8][4];
        #pragma unroll
        for (int nt = 0; nt < 8; ++nt)
            #pragma unroll
            for (int q = 0; q < 4; ++q) s[nt][q] = 0.f;

        {
            const int quad = lane >> 3;
            #pragma unroll
            for (int np = 0; np < 4; ++np) {
                int brow = np * 16 + ((quad >> 1) << 3) + (lane & 7);
                #pragma unroll
                for (int ks = 0; ks < 4; ++ks) {
                    uint32_t boff = (uint32_t)(brow * AT_STRIDE + ks * 16 + ((quad & 1) << 3)) * 2;
                    uint32_t Bh[4], Bl[4];
                    ldsm4(Bh, aKh + boff);
                    ldsm4(Bl, aKl + boff);
                    mma16816(s[2*np],   Qh[ks], Bh[0], Bh[1]);
                    mma16816(s[2*np],   Qh[ks], Bl[0], Bl[1]);
                    mma16816(s[2*np],   Ql[ks], Bh[0], Bh[1]);
                    mma16816(s[2*np+1], Qh[ks], Bh[2], Bh[3]);
                    mma16816(s[2*np+1], Qh[ks], Bl[2], Bl[3]);
                    mma16816(s[2*np+1], Ql[ks], Bh[2], Bh[3]);
                }
            }
        }

        if (jt == qt) {
            #pragma unroll
            for (int nt = 0; nt < 8; ++nt) {
                int col0 = nt * 8 + mycol;
                if (col0     > myrow)     s[nt][0] = IGNOREV;
                if (col0 + 1 > myrow)     s[nt][1] = IGNOREV;
                if (col0     > myrow + 8) s[nt][2] = IGNOREV;
                if (col0 + 1 > myrow + 8) s[nt][3] = IGNOREV;
            }
        }

        float mx0 = -1e30f, mx1 = -1e30f;
        #pragma unroll
        for (int nt = 0; nt < 8; ++nt) {
            mx0 = fmaxf(mx0, fmaxf(s[nt][0], s[nt][1]));
            mx1 = fmaxf(mx1, fmaxf(s[nt][2], s[nt][3]));
        }
        #pragma unroll
        for (int o = 1; o < 4; o <<= 1) {
            mx0 = fmaxf(mx0, __shfl_xor_sync(0xffffffffu, mx0, o));
            mx1 = fmaxf(mx1, __shfl_xor_sync(0xffffffffu, mx1, o));
        }
        float nm0 = fmaxf(m0, mx0), nm1 = fmaxf(m1, mx1);
        float al0 = __expf(m0 - nm0), al1 = __expf(m1 - nm1);
        float rs0 = 0.f, rs1 = 0.f;
        #pragma unroll
        for (int nt = 0; nt < 8; ++nt) {
            s[nt][0] = __expf(s[nt][0] - nm0); rs0 += s[nt][0];
            s[nt][1] = __expf(s[nt][1] - nm0); rs0 += s[nt][1];
            s[nt][2] = __expf(s[nt][2] - nm1); rs1 += s[nt][2];
            s[nt][3] = __expf(s[nt][3] - nm1); rs1 += s[nt][3];
        }
        #pragma unroll
        for (int o = 1; o < 4; o <<= 1) {
            rs0 += __shfl_xor_sync(0xffffffffu, rs0, o);
            rs1 += __shfl_xor_sync(0xffffffffu, rs1, o);
        }
        l0 = l0 * al0 + rs0; l1 = l1 * al1 + rs1;
        m0 = nm0; m1 = nm1;
        #pragma unroll
        for (int nt = 0; nt < 8; ++nt) {
            acc[nt][0] *= al0; acc[nt][1] *= al0;
            acc[nt][2] *= al1; acc[nt][3] *= al1;
        }

        #pragma unroll
        for (int kt = 0; kt < 4; ++kt) {
            uint32_t Ph[4], Pl[4];
            packsplit(s[2*kt][0],   s[2*kt][1],   Ph[0], Pl[0]);
            packsplit(s[2*kt][2],   s[2*kt][3],   Ph[1], Pl[1]);
            packsplit(s[2*kt+1][0], s[2*kt+1][1], Ph[2], Pl[2]);
            packsplit(s[2*kt+1][2], s[2*kt+1][3], Ph[3], Pl[3]);
            int vrow = kt * 16 + (lane & 15);
            #pragma unroll
            for (int nd = 0; nd < 4; ++nd) {
                uint32_t voff = (uint32_t)(vrow * AT_STRIDE + nd * 16 + ((lane >> 4) << 3)) * 2;
                uint32_t Vhf[4], Vlf[4];
                ldsm4t(Vhf, aVh + voff);
                ldsm4t(Vlf, aVl + voff);
                mma16816(acc[2*nd],   Ph, Vhf[0], Vhf[1]);
                mma16816(acc[2*nd],   Ph, Vlf[0], Vlf[1]);
                mma16816(acc[2*nd],   Pl, Vhf[0], Vhf[1]);
                mma16816(acc[2*nd+1], Ph, Vhf[2], Vhf[3]);
                mma16816(acc[2*nd+1], Ph, Vlf[2], Vlf[3]);
                mma16816(acc[2*nd+1], Pl, Vhf[2], Vhf[3]);
            }
        }
        __syncthreads();
    }

    float inv0 = 1.f / l0, inv1 = 1.f / l1;
    int rowA = qt * 64 + myrow;
    #pragma unroll
    for (int nt = 0; nt < 8; ++nt) {
        int col = h * 64 + nt * 8 + mycol;
        size_t offA = ((size_t)b * S_ + rowA) * D_ + col;
        size_t offB = ((size_t)b * S_ + rowA + 8) * D_ + col;
        uint32_t ph, pl;
        packsplit(acc[nt][0] * inv0, acc[nt][1] * inv0, ph, pl);
        *(uint32_t*)(z_hi + offA) = ph;
        *(uint32_t*)(z_lo + offA) = pl;
        packsplit(acc[nt][2] * inv1, acc[nt][3] * inv1, ph, pl);
        *(uint32_t*)(z_hi + offB) = ph;
        *(uint32_t*)(z_lo + offB) = pl;
    }
}

// ---------------- Host launch ----------------
template <typename Tp>
static Tp* sym_addr(const void* sym) {
    void* p = nullptr;
    cudaGetSymbolAddress(&p, sym);
    return (Tp*)p;
}

extern "C" void kernel_launch(void* const* d_in, const int* in_sizes, int n_in,
                              void* d_out, int out_size) {
    const float* x     = (const float*)d_in[0];
    const float* W_Q   = (const float*)d_in[1];
    const float* W_K   = (const float*)d_in[2];
    const float* W_V   = (const float*)d_in[3];
    const float* W_O   = (const float*)d_in[4];
    const float* b_Q   = (const float*)d_in[5];
    const float* b_K   = (const float*)d_in[6];
    const float* b_V   = (const float*)d_in[7];
    const float* b_O   = (const float*)d_in[8];
    const float* W_in  = (const float*)d_in[9];
    const float* b_in  = (const float*)d_in[10];
    const float* W_out = (const float*)d_in[11];
    const float* b_out = (const float*)d_in[12];
    float* out = (float*)d_out;

    __nv_bfloat16* xn_hi  = sym_addr<__nv_bfloat16>(g_xn_hi);
    __nv_bfloat16* xn_lo  = sym_addr<__nv_bfloat16>(g_xn_lo);
    float*         qkv    = sym_addr<float>(g_qkv);
    __nv_bfloat16* z_hi   = sym_addr<__nv_bfloat16>(g_z_hi);
    __nv_bfloat16* z_lo   = sym_addr<__nv_bfloat16>(g_z_lo);
    float*         rmid   = sym_addr<float>(g_rmid);
    __nv_bfloat16* m_hi   = sym_addr<__nv_bfloat16>(g_m_hi);
    __nv_bfloat16* m_lo   = sym_addr<__nv_bfloat16>(g_m_lo);
    __nv_bfloat16* hid_hi = sym_addr<__nv_bfloat16>(g_hid_hi);
    __nv_bfloat16* hid_lo = sym_addr<__nv_bfloat16>(g_hid_lo);
    __nv_bfloat16* Wqkv_hi = sym_addr<__nv_bfloat16>(g_Wqkv_hi);
    __nv_bfloat16* Wqkv_lo = sym_addr<__nv_bfloat16>(g_Wqkv_lo);
    __nv_bfloat16* Wo_hi   = sym_addr<__nv_bfloat16>(g_Wo_hi);
    __nv_bfloat16* Wo_lo   = sym_addr<__nv_bfloat16>(g_Wo_lo);
    __nv_bfloat16* Win_hi  = sym_addr<__nv_bfloat16>(g_Win_hi);
    __nv_bfloat16* Win_lo  = sym_addr<__nv_bfloat16>(g_Win_lo);
    __nv_bfloat16* Wout_hi = sym_addr<__nv_bfloat16>(g_Wout_hi);
    __nv_bfloat16* Wout_lo = sym_addr<__nv_bfloat16>(g_Wout_lo);
    float*         bqkv    = sym_addr<float>(g_bqkv);

    cudaFuncSetAttribute(gemm_mma<0,0,0>, cudaFuncAttributeMaxDynamicSharedMemorySize, GEMM_SMEM);
    cudaFuncSetAttribute(gemm_mma<0,1,0>, cudaFuncAttributeMaxDynamicSharedMemorySize, GEMM_SMEM);
    cudaFuncSetAttribute(gemm_mma<1,0,1>, cudaFuncAttributeMaxDynamicSharedMemorySize, GEMM_SMEM);

    // Fused weight splits + bias concat (1 launch) + W_O gather (1 launch)
    const int total4 = N4_ALL + 3072;
    split_all_kernel<<<(total4 + 255) / 256, 256>>>(
        W_Q, W_K, W_V, W_in, W_out,
        Wqkv_hi, Wqkv_lo, Win_hi, Win_lo, Wout_hi, Wout_lo,
        b_Q, b_K, b_V, bqkv);
    wo_split_kernel<<<(D_ * D_) / 256, 256>>>(W_O, Wo_hi, Wo_lo);

    // LN1 -> xn hi/lo
    ln_split_kernel<<<T_, 256>>>(x, xn_hi, xn_lo);

    // Fused QKV projection: qkv[T,3072]
    gemm_mma<0,0,0><<<dim3(3072 / 128, T_ / 128), 256, GEMM_SMEM>>>(
        T_, 3072, D_, xn_hi, xn_lo, Wqkv_hi, Wqkv_lo, bqkv, nullptr, qkv, nullptr, nullptr);

    // Tensor-core attention -> z hi/lo
    attn_mma_kernel<<<dim3(S_ / 64, B_ * H_), 128>>>(qkv, z_hi, z_lo);

    // O projection + residual: rmid = x + z @ Wo^T + b_O
    gemm_mma<0,1,0><<<dim3(D_ / 128, T_ / 128), 256, GEMM_SMEM>>>(
        T_, D_, D_, z_hi, z_lo, Wo_hi, Wo_lo, b_O, x, rmid, nullptr, nullptr);

    // LN2 -> m hi/lo
    ln_split_kernel<<<T_, 256>>>(rmid, m_hi, m_lo);

    // MLP in + gelu -> hid hi/lo (bf16 split output)
    gemm_mma<1,0,1><<<dim3(DM_ / 128, T_ / 128), 256, GEMM_SMEM>>>(
        T_, DM_, D_, m_hi, m_lo, Win_hi, Win_lo, b_in, nullptr, nullptr, hid_hi, hid_lo);

    // MLP out + residual -> final output
    gemm_mma<0,1,0><<<dim3(D_ / 128, T_ / 128), 256, GEMM_SMEM>>>(
        T_, D_, DM_, hid_hi, hid_lo, Wout_hi, Wout_lo, b_out, rmid, out, nullptr, nullptr);
}

// round 16
// speedup vs baseline: 1.9557x; 1.0223x over previous
#include <cuda_runtime.h>
#include <cuda_bf16.h>
#include <math.h>
#include <stdint.h>

// ---------------- Problem dims ----------------
#define B_      2
#define S_      2048
#define T_      4096          // B*S tokens
#define D_      1024
#define H_      16
#define DH_     64
#define DM_     4096
#define EPSV    1e-5f
#define IGNOREV -100000.0f

// ---------------- Small helpers ----------------
__device__ __forceinline__ uint32_t smem_u32(const void* p) {
    uint32_t a;
    asm("{ .reg .u64 t; cvta.to.shared.u64 t, %1; cvt.u32.u64 %0, t; }" : "=r"(a) : "l"(p));
    return a;
}
__device__ __forceinline__ void split2(float v, __nv_bfloat16& h, __nv_bfloat16& l) {
    h = __float2bfloat16(v);
    l = __float2bfloat16(v - __bfloat162float(h));
}
__device__ __forceinline__ float gelu_new_f(float x) {
    float x3 = x * x * x;
    return 0.5f * x * (1.0f + tanhf(0.7978845608028654f * (x + 0.044715f * x3)));
}

// ---------------- Baseline-PTX tensor-core primitives (sm_80+; valid on sm_103) ----
__device__ __forceinline__ void cp16(uint32_t saddr, const void* g) {
    asm volatile("cp.async.cg.shared.global [%0], [%1], 16;" :: "r"(saddr), "l"(g));
}
__device__ __forceinline__ void cp_commit() {
    asm volatile("cp.async.commit_group;" ::: "memory");
}
template <int N>
__device__ __forceinline__ void cp_wait() {
    asm volatile("cp.async.wait_group %0;" :: "n"(N) : "memory");
}
__device__ __forceinline__ void ldsm4(uint32_t (&r)[4], uint32_t a) {
    asm volatile("ldmatrix.sync.aligned.m8n8.x4.shared.b16 {%0,%1,%2,%3}, [%4];"
                 : "=r"(r[0]), "=r"(r[1]), "=r"(r[2]), "=r"(r[3]) : "r"(a));
}
__device__ __forceinline__ void ldsm4t(uint32_t (&r)[4], uint32_t a) {
    asm volatile("ldmatrix.sync.aligned.m8n8.x4.trans.shared.b16 {%0,%1,%2,%3}, [%4];"
                 : "=r"(r[0]), "=r"(r[1]), "=r"(r[2]), "=r"(r[3]) : "r"(a));
}
__device__ __forceinline__ void mma16816(float (&c)[4], const uint32_t (&a)[4],
                                         uint32_t b0, uint32_t b1) {
    asm volatile(
        "mma.sync.aligned.m16n8k16.row.col.f32.bf16.bf16.f32 "
        "{%0,%1,%2,%3}, {%4,%5,%6,%7}, {%8,%9}, {%0,%1,%2,%3};"
        : "+f"(c[0]), "+f"(c[1]), "+f"(c[2]), "+f"(c[3])
        : "r"(a[0]), "r"(a[1]), "r"(a[2]), "r"(a[3]), "r"(b0), "r"(b1));
}

// ---------------- Scratch (static device globals; no allocation) ----------------
__device__ __nv_bfloat16 g_xn_hi [T_ * D_];
__device__ __nv_bfloat16 g_xn_lo [T_ * D_];
__device__ float         g_qkv   [(size_t)T_ * 3072];
__device__ __nv_bfloat16 g_z_hi  [T_ * D_];
__device__ __nv_bfloat16 g_z_lo  [T_ * D_];
__device__ float         g_rmid  [T_ * D_];
__device__ __nv_bfloat16 g_m_hi  [T_ * D_];
__device__ __nv_bfloat16 g_m_lo  [T_ * D_];
__device__ __nv_bfloat16 g_hid_hi[(size_t)T_ * DM_];
__device__ __nv_bfloat16 g_hid_lo[(size_t)T_ * DM_];
__device__ __nv_bfloat16 g_Wqkv_hi[3 * D_ * D_];
__device__ __nv_bfloat16 g_Wqkv_lo[3 * D_ * D_];
__device__ __nv_bfloat16 g_Wo_hi [D_ * D_];
__device__ __nv_bfloat16 g_Wo_lo [D_ * D_];
__device__ __nv_bfloat16 g_Win_hi[(size_t)DM_ * D_];
__device__ __nv_bfloat16 g_Win_lo[(size_t)DM_ * D_];
__device__ __nv_bfloat16 g_Wout_hi[(size_t)D_ * DM_];
__device__ __nv_bfloat16 g_Wout_lo[(size_t)D_ * DM_];
__device__ float         g_bqkv  [3072];

// ---------------- Fused weight split (all straight [N,K] weights + bias concat) ----
__device__ __forceinline__ void split4_store(float4 v,
                                             __nv_bfloat16* __restrict__ hi,
                                             __nv_bfloat16* __restrict__ lo, int i) {
    __nv_bfloat16 h0,h1,h2,h3,l0,l1,l2,l3;
    split2(v.x,h0,l0); split2(v.y,h1,l1); split2(v.z,h2,l2); split2(v.w,h3,l3);
    uint32_t ph0 = (uint32_t)__bfloat16_as_ushort(h0) | ((uint32_t)__bfloat16_as_ushort(h1) << 16);
    uint32_t ph1 = (uint32_t)__bfloat16_as_ushort(h2) | ((uint32_t)__bfloat16_as_ushort(h3) << 16);
    uint32_t pl0 = (uint32_t)__bfloat16_as_ushort(l0) | ((uint32_t)__bfloat16_as_ushort(l1) << 16);
    uint32_t pl1 = (uint32_t)__bfloat16_as_ushort(l2) | ((uint32_t)__bfloat16_as_ushort(l3) << 16);
    ((uint2*)hi)[i] = make_uint2(ph0, ph1);
    ((uint2*)lo)[i] = make_uint2(pl0, pl1);
}

#define N4_QKV1 (D_ * D_ / 4)
#define N4_MLP  (DM_ * D_ / 4)
#define N4_ALL  (3 * N4_QKV1 + 2 * N4_MLP)

__global__ void split_all_kernel(const float* __restrict__ WQ, const float* __restrict__ WK,
                                 const float* __restrict__ WV, const float* __restrict__ Win,
                                 const float* __restrict__ Wout,
                                 __nv_bfloat16* __restrict__ Wqkv_hi, __nv_bfloat16* __restrict__ Wqkv_lo,
                                 __nv_bfloat16* __restrict__ Win_hi,  __nv_bfloat16* __restrict__ Win_lo,
                                 __nv_bfloat16* __restrict__ Wout_hi, __nv_bfloat16* __restrict__ Wout_lo,
                                 const float* __restrict__ bq, const float* __restrict__ bk,
                                 const float* __restrict__ bv, float* __restrict__ bqkv) {
    int i = blockIdx.x * 256 + threadIdx.x;
    if (i < N4_ALL) {
        if (i < 3 * N4_QKV1) {
            int seg = i / N4_QKV1, j = i - seg * N4_QKV1;
            const float* src = (seg == 0) ? WQ : (seg == 1) ? WK : WV;
            split4_store(((const float4*)src)[j],
                         Wqkv_hi + (size_t)seg * D_ * D_, Wqkv_lo + (size_t)seg * D_ * D_, j);
        } else if (i < 3 * N4_QKV1 + N4_MLP) {
            int j = i - 3 * N4_QKV1;
            split4_store(((const float4*)Win)[j], Win_hi, Win_lo, j);
        } else {
            int j = i - 3 * N4_QKV1 - N4_MLP;
            split4_store(((const float4*)Wout)[j], Wout_hi, Wout_lo, j);
        }
    } else {
        int j = i - N4_ALL;
        if (j < 3072) {
            float v = (j < 1024) ? bq[j] : (j < 2048) ? bk[j - 1024] : bv[j - 2048];
            bqkv[j] = v;
        }
    }
}

// W_O [H, D, DH] -> [N=d][K=h*64+dh] bf16 hi/lo (gather pattern)
__global__ void wo_split_kernel(const float* __restrict__ wo,
                                __nv_bfloat16* __restrict__ hi,
                                __nv_bfloat16* __restrict__ lo) {
    int idx = blockIdx.x * 256 + threadIdx.x;
    int d  = idx >> 10;
    int kk = idx & 1023;
    int h  = kk >> 6, dh = kk & 63;
    float v = wo[(size_t)h * D_ * DH_ + (size_t)d * DH_ + dh];
    __nv_bfloat16 hh, ll; split2(v, hh, ll);
    hi[idx] = hh; lo[idx] = ll;
}

// ---------------- LayerNorm -> bf16 hi/lo ----------------
__global__ void ln_split_kernel(const float* __restrict__ src,
                                __nv_bfloat16* __restrict__ hi,
                                __nv_bfloat16* __restrict__ lo) {
    int row = blockIdx.x;
    float4 vv = ((const float4*)(src + (size_t)row * D_))[threadIdx.x];
    float s  = vv.x + vv.y + vv.z + vv.w;
    float s2 = vv.x*vv.x + vv.y*vv.y + vv.z*vv.z + vv.w*vv.w;
    #pragma unroll
    for (int o = 16; o > 0; o >>= 1) {
        s  += __shfl_xor_sync(0xffffffffu, s,  o);
        s2 += __shfl_xor_sync(0xffffffffu, s2, o);
    }
    __shared__ float ws[8], ws2[8];
    __shared__ float s_mean, s_r;
    int w = threadIdx.x >> 5;
    if ((threadIdx.x & 31) == 0) { ws[w] = s; ws2[w] = s2; }
    __syncthreads();
    if (threadIdx.x == 0) {
        float a = 0.f, b2 = 0.f;
        #pragma unroll
        for (int i = 0; i < 8; i++) { a += ws[i]; b2 += ws2[i]; }
        float mean = a * (1.f / D_);
        float var  = b2 * (1.f / D_) - mean * mean;
        s_mean = mean; s_r = rsqrtf(var + EPSV);
    }
    __syncthreads();
    float mean = s_mean, r = s_r;
    float o0 = (vv.x - mean) * r, o1 = (vv.y - mean) * r;
    float o2 = (vv.z - mean) * r, o3 = (vv.w - mean) * r;
    __nv_bfloat16 h0,h1,h2,h3,l0,l1,l2,l3;
    split2(o0,h0,l0); split2(o1,h1,l1); split2(o2,h2,l2); split2(o3,h3,l3);
    uint32_t ph0 = (uint32_t)__bfloat16_as_ushort(h0) | ((uint32_t)__bfloat16_as_ushort(h1) << 16);
    uint32_t ph1 = (uint32_t)__bfloat16_as_ushort(h2) | ((uint32_t)__bfloat16_as_ushort(h3) << 16);
    uint32_t pl0 = (uint32_t)__bfloat16_as_ushort(l0) | ((uint32_t)__bfloat16_as_ushort(l1) << 16);
    uint32_t pl1 = (uint32_t)__bfloat16_as_ushort(l2) | ((uint32_t)__bfloat16_as_ushort(l3) << 16);
    size_t base = (size_t)row * D_ + threadIdx.x * 4;
    ((uint2*)(hi + base))[0] = make_uint2(ph0, ph1);
    ((uint2*)(lo + base))[0] = make_uint2(pl0, pl1);
}

// ================= mma.sync bf16-split GEMM — 2-stage, 2 CTAs/SM =================
#define GSM_STRIDE 40
#define GSM_ARR_B  (128 * GSM_STRIDE * 2)     // 10240 B
#define GSM_STAGE_B (4 * GSM_ARR_B)           // 40960 B
#define GEMM_SMEM  (2 * GSM_STAGE_B)          // 81920 B -> 2 CTAs/SM

__device__ __forceinline__ void fill_stage(
    uint32_t sbase,
    const __nv_bfloat16* __restrict__ Ahi, const __nv_bfloat16* __restrict__ Alo,
    const __nv_bfloat16* __restrict__ Bhi, const __nv_bfloat16* __restrict__ Blo,
    int m0, int n0, int kb, int K, int tid) {
    int row = tid & 127;
    int kc0 = tid >> 7;
    #pragma unroll
    for (int i = 0; i < 2; ++i) {
        int kc = kc0 + i * 2;
        uint32_t soff = (uint32_t)(row * GSM_STRIDE + kc * 8) * 2;
        size_t ga = (size_t)(m0 + row) * K + kb + kc * 8;
        size_t gb = (size_t)(n0 + row) * K + kb + kc * 8;
        cp16(sbase +                 soff, Ahi + ga);
        cp16(sbase + GSM_ARR_B +     soff, Alo + ga);
        cp16(sbase + 2 * GSM_ARR_B + soff, Bhi + gb);
        cp16(sbase + 3 * GSM_ARR_B + soff, Blo + gb);
    }
}

template <int ACT, int RES, int OUTBF16>
__global__ void __launch_bounds__(256, 2)
gemm_mma(int M, int N, int K,
         const __nv_bfloat16* __restrict__ Ahi, const __nv_bfloat16* __restrict__ Alo,
         const __nv_bfloat16* __restrict__ Bhi, const __nv_bfloat16* __restrict__ Blo,
         const float* __restrict__ bias, const float* __restrict__ resid,
         float* __restrict__ Cf,
         __nv_bfloat16* __restrict__ Chi, __nv_bfloat16* __restrict__ Clo) {
    extern __shared__ char sm_raw[];
    uint32_t sb = smem_u32(sm_raw);
    const int tid  = threadIdx.x;
    const int wid  = tid >> 5;
    const int lane = tid & 31;
    const int m0 = blockIdx.y * 128;
    const int n0 = blockIdx.x * 128;
    const int wr0 = (wid >> 1) * 32;
    const int wc0 = (wid & 1) * 64;

    float acc[2][8][4];
    #pragma unroll
    for (int mt = 0; mt < 2; ++mt)
        #pragma unroll
        for (int j = 0; j < 8; ++j)
            #pragma unroll
            for (int q = 0; q < 4; ++q) acc[mt][j][q] = 0.f;

    const int nst = K >> 5;

    // Prefill stage 0
    fill_stage(sb, Ahi, Alo, Bhi, Blo, m0, n0, 0, K, tid);
    cp_commit();

    for (int c = 0; c < nst; ++c) {
        // Fill the other buffer (safe: all warps synced after computing it last iter)
        if (c + 1 < nst)
            fill_stage(sb + (uint32_t)((c + 1) & 1) * GSM_STAGE_B,
                       Ahi, Alo, Bhi, Blo, m0, n0, (c + 1) << 5, K, tid);
        cp_commit();
        cp_wait<1>();        // retire stage c's group (always-commit accounting)
        __syncthreads();

        uint32_t st = sb + (uint32_t)(c & 1) * GSM_STAGE_B;
        #pragma unroll
        for (int ks = 0; ks < 2; ++ks) {
            const int k0 = ks * 16;
            uint32_t Ah[2][4], Al[2][4];
            #pragma unroll
            for (int mt = 0; mt < 2; ++mt) {
                int arow = wr0 + mt * 16 + (lane & 15);
                uint32_t aoff = (uint32_t)(arow * GSM_STRIDE + k0 + ((lane >> 4) << 3)) * 2;
                ldsm4(Ah[mt], st + aoff);
                ldsm4(Al[mt], st + GSM_ARR_B + aoff);
            }
            // Stream B fragments per 16-col slice (8 live regs, not 64)
            #pragma unroll
            for (int np = 0; np < 4; ++np) {
                int quad = lane >> 3;
                int brow = wc0 + np * 16 + ((quad >> 1) << 3) + (lane & 7);
                uint32_t boff = (uint32_t)(brow * GSM_STRIDE + k0 + ((quad & 1) << 3)) * 2;
                uint32_t Bh[4], Bl[4];
                ldsm4(Bh, st + 2 * GSM_ARR_B + boff);
                ldsm4(Bl, st + 3 * GSM_ARR_B + boff);
                #pragma unroll
                for (int mt = 0; mt < 2; ++mt) {
                    mma16816(acc[mt][2*np],   Ah[mt], Bh[0], Bh[1]);
                    mma16816(acc[mt][2*np],   Ah[mt], Bl[0], Bl[1]);
                    mma16816(acc[mt][2*np],   Al[mt], Bh[0], Bh[1]);
                    mma16816(acc[mt][2*np+1], Ah[mt], Bh[2], Bh[3]);
                    mma16816(acc[mt][2*np+1], Ah[mt], Bl[2], Bl[3]);
                    mma16816(acc[mt][2*np+1], Al[mt], Bh[2], Bh[3]);
                }
            }
        }
        __syncthreads();     // all warps done with stage c before it is refilled
    }

    const int qrow = lane >> 2;
    const int qcol = (lane & 3) * 2;
    #pragma unroll
    for (int mt = 0; mt < 2; ++mt)
        #pragma unroll
        for (int j = 0; j < 8; ++j)
            #pragma unroll
            for (int half = 0; half < 2; ++half) {
                int row = m0 + wr0 + mt * 16 + qrow + half * 8;
                int col = n0 + wc0 + j * 8 + qcol;
                float v0 = acc[mt][j][half * 2 + 0] + bias[col];
                float v1 = acc[mt][j][half * 2 + 1] + bias[col + 1];
                if (ACT) { v0 = gelu_new_f(v0); v1 = gelu_new_f(v1); }
                size_t off = (size_t)row * N + col;
                if (RES) {
                    float2 rr = *(const float2*)(resid + off);
                    v0 += rr.x; v1 += rr.y;
                }
                if (!OUTBF16) {
                    *(float2*)(Cf + off) = make_float2(v0, v1);
                } else {
                    __nv_bfloat16 h0, h1, l0, l1;
                    split2(v0, h0, l0);
                    split2(v1, h1, l1);
                    uint32_t ph = (uint32_t)__bfloat16_as_ushort(h0) |
                                  ((uint32_t)__bfloat16_as_ushort(h1) << 16);
                    uint32_t pl = (uint32_t)__bfloat16_as_ushort(l0) |
                                  ((uint32_t)__bfloat16_as_ushort(l1) << 16);
                    *(uint32_t*)(Chi + off) = ph;
                    *(uint32_t*)(Clo + off) = pl;
                }
            }
}

// ================= Tensor-core causal flash attention (unchanged, verified) =======
#define AT_STRIDE 72

__device__ __forceinline__ void at_fill64(const float* __restrict__ src,
                                          __nv_bfloat16* __restrict__ hi,
                                          __nv_bfloat16* __restrict__ lo,
                                          int tid, float scale) {
    int row = tid >> 1;
    int c0  = (tid & 1) * 32;
    const float4* s4 = (const float4*)(src + (size_t)row * 3072 + c0);
    #pragma unroll
    for (int i = 0; i < 8; ++i) {
        float4 v = s4[i];
        __nv_bfloat16 h0,h1,h2,h3,l0,l1,l2,l3;
        split2(v.x * scale, h0, l0); split2(v.y * scale, h1, l1);
        split2(v.z * scale, h2, l2); split2(v.w * scale, h3, l3);
        uint32_t ph0 = (uint32_t)__bfloat16_as_ushort(h0) | ((uint32_t)__bfloat16_as_ushort(h1) << 16);
        uint32_t ph1 = (uint32_t)__bfloat16_as_ushort(h2) | ((uint32_t)__bfloat16_as_ushort(h3) << 16);
        uint32_t pl0 = (uint32_t)__bfloat16_as_ushort(l0) | ((uint32_t)__bfloat16_as_ushort(l1) << 16);
        uint32_t pl1 = (uint32_t)__bfloat16_as_ushort(l2) | ((uint32_t)__bfloat16_as_ushort(l3) << 16);
        int off = row * AT_STRIDE + c0 + i * 4;
        *(uint2*)(hi + off) = make_uint2(ph0, ph1);
        *(uint2*)(lo + off) = make_uint2(pl0, pl1);
    }
}

__device__ __forceinline__ void packsplit(float f0, float f1, uint32_t& ph, uint32_t& pl) {
    __nv_bfloat16 h0, l0, h1, l1;
    split2(f0, h0, l0); split2(f1, h1, l1);
    ph = (uint32_t)__bfloat16_as_ushort(h0) | ((uint32_t)__bfloat16_as_ushort(h1) << 16);
    pl = (uint32_t)__bfloat16_as_ushort(l0) | ((uint32_t)__bfloat16_as_ushort(l1) << 16);
}

__global__ void __launch_bounds__(128)
attn_mma_kernel(const float* __restrict__ qkv,
                __nv_bfloat16* __restrict__ z_hi, __nv_bfloat16* __restrict__ z_lo) {
    __shared__ __nv_bfloat16 sKh[64 * AT_STRIDE], sKl[64 * AT_STRIDE];
    __shared__ __nv_bfloat16 sVh[64 * AT_STRIDE], sVl[64 * AT_STRIDE];

    const int tid  = threadIdx.x;
    const int wid  = tid >> 5;
    const int lane = tid & 31;
    const int qt = (int)gridDim.x - 1 - (int)blockIdx.x;
    const int bh = blockIdx.y;
    const int b = bh >> 4, h = bh & 15;

    const float* qp = qkv + (size_t)b * S_ * 3072 + h * 64;
    const float* kp = qp + 1024;
    const float* vp = qp + 2048;

    uint32_t aKh = smem_u32(sKh), aKl = smem_u32(sKl);
    uint32_t aVh = smem_u32(sVh), aVl = smem_u32(sVl);

    at_fill64(qp + (size_t)(qt * 64) * 3072, sKh, sKl, tid, 0.125f);
    __syncthreads();
    uint32_t Qh[4][4], Ql[4][4];
    {
        int arow = wid * 16 + (lane & 15);
        #pragma unroll
        for (int ks = 0; ks < 4; ++ks) {
            uint32_t off = (uint32_t)(arow * AT_STRIDE + ks * 16 + ((lane >> 4) << 3)) * 2;
            ldsm4(Qh[ks], aKh + off);
            ldsm4(Ql[ks], aKl + off);
        }
    }
    __syncthreads();

    float m0 = -1e30f, m1 = -1e30f, l0 = 0.f, l1 = 0.f;
    float acc[8][4];
    #pragma unroll
    for (int nt = 0; nt < 8; ++nt)
        #pragma unroll
        for (int q = 0; q < 4; ++q) acc[nt][q] = 0.f;

    const int myrow = wid * 16 + (lane >> 2);
    const int mycol = (lane & 3) * 2;

    for (int jt = 0; jt <= qt; ++jt) {
        at_fill64(kp + (size_t)(jt * 64) * 3072, sKh, sKl, tid, 1.0f);
        at_fill64(vp + (size_t)(jt * 64) * 3072, sVh, sVl, tid, 1.0f);
        __syncthreads();

        float s[8][4];
        #pragma unroll
        for (int nt = 0; nt < 8; ++nt)
            #pragma unroll
            for (int q = 0; q < 4; ++q) s[nt][q] = 0.f;

        {
            const int quad = lane >> 3;
            #pragma unroll
            for (int np = 0; np < 4; ++np) {
                int brow = np * 16 + ((quad >> 1) << 3) + (lane & 7);
                #pragma unroll
                for (int ks = 0; ks < 4; ++ks) {
                    uint32_t boff = (uint32_t)(brow * AT_STRIDE + ks * 16 + ((quad & 1) << 3)) * 2;
                    uint32_t Bh[4], Bl[4];
                    ldsm4(Bh, aKh + boff);
                    ldsm4(Bl, aKl + boff);
                    mma16816(s[2*np],   Qh[ks], Bh[0], Bh[1]);
                    mma16816(s[2*np],   Qh[ks], Bl[0], Bl[1]);
                    mma16816(s[2*np],   Ql[ks], Bh[0], Bh[1]);
                    mma16816(s[2*np+1], Qh[ks], Bh[2], Bh[3]);
                    mma16816(s[2*np+1], Qh[ks], Bl[2], Bl[3]);
                    mma16816(s[2*np+1], Ql[ks], Bh[2], Bh[3]);
                }
            }
        }

        if (jt == qt) {
            #pragma unroll
            for (int nt = 0; nt < 8; ++nt) {
                int col0 = nt * 8 + mycol;
                if (col0     > myrow)     s[nt][0] = IGNOREV;
                if (col0 + 1 > myrow)     s[nt][1] = IGNOREV;
                if (col0     > myrow + 8) s[nt][2] = IGNOREV;
                if (col0 + 1 > myrow + 8) s[nt][3] = IGNOREV;
            }
        }

        float mx0 = -1e30f, mx1 = -1e30f;
        #pragma unroll
        for (int nt = 0; nt < 8; ++nt) {
            mx0 = fmaxf(mx0, fmaxf(s[nt][0], s[nt][1]));
            mx1 = fmaxf(mx1, fmaxf(s[nt][2], s[nt][3]));
        }
        #pragma unroll
        for (int o = 1; o < 4; o <<= 1) {
            mx0 = fmaxf(mx0, __shfl_xor_sync(0xffffffffu, mx0, o));
            mx1 = fmaxf(mx1, __shfl_xor_sync(0xffffffffu, mx1, o));
        }
        float nm0 = fmaxf(m0, mx0), nm1 = fmaxf(m1, mx1);
        float al0 = __expf(m0 - nm0), al1 = __expf(m1 - nm1);
        float rs0 = 0.f, rs1 = 0.f;
        #pragma unroll
        for (int nt = 0; nt < 8; ++nt) {
            s[nt][0] = __expf(s[nt][0] - nm0); rs0 += s[nt][0];
            s[nt][1] = __expf(s[nt][1] - nm0); rs0 += s[nt][1];
            s[nt][2] = __expf(s[nt][2] - nm1); rs1 += s[nt][2];
            s[nt][3] = __expf(s[nt][3] - nm1); rs1 += s[nt][3];
        }
        #pragma unroll
        for (int o = 1; o < 4; o <<= 1) {
            rs0 += __shfl_xor_sync(0xffffffffu, rs0, o);
            rs1 += __shfl_xor_sync(0xffffffffu, rs1, o);
        }
        l0 = l0 * al0 + rs0; l1 = l1 * al1 + rs1;
        m0 = nm0; m1 = nm1;
        #pragma unroll
        for (int nt = 0; nt < 8; ++nt) {
            acc[nt][0] *= al0; acc[nt][1] *= al0;
            acc[nt][2] *= al1; acc[nt][3] *= al1;
        }

        #pragma unroll
        for (int kt = 0; kt < 4; ++kt) {
            uint32_t Ph[4], Pl[4];
            packsplit(s[2*kt][0],   s[2*kt][1],   Ph[0], Pl[0]);
            packsplit(s[2*kt][2],   s[2*kt][3],   Ph[1], Pl[1]);
            packsplit(s[2*kt+1][0], s[2*kt+1][1], Ph[2], Pl[2]);
            packsplit(s[2*kt+1][2], s[2*kt+1][3], Ph[3], Pl[3]);
            int vrow = kt * 16 + (lane & 15);
            #pragma unroll
            for (int nd = 0; nd < 4; ++nd) {
                uint32_t voff = (uint32_t)(vrow * AT_STRIDE + nd * 16 + ((lane >> 4) << 3)) * 2;
                uint32_t Vhf[4], Vlf[4];
                ldsm4t(Vhf, aVh + voff);
                ldsm4t(Vlf, aVl + voff);
                mma16816(acc[2*nd],   Ph, Vhf[0], Vhf[1]);
                mma16816(acc[2*nd],   Ph, Vlf[0], Vlf[1]);
                mma16816(acc[2*nd],   Pl, Vhf[0], Vhf[1]);
                mma16816(acc[2*nd+1], Ph, Vhf[2], Vhf[3]);
                mma16816(acc[2*nd+1], Ph, Vlf[2], Vlf[3]);
                mma16816(acc[2*nd+1], Pl, Vhf[2], Vhf[3]);
            }
        }
        __syncthreads();
    }

    float inv0 = 1.f / l0, inv1 = 1.f / l1;
    int rowA = qt * 64 + myrow;
    #pragma unroll
    for (int nt = 0; nt < 8; ++nt) {
        int col = h * 64 + nt * 8 + mycol;
        size_t offA = ((size_t)b * S_ + rowA) * D_ + col;
        size_t offB = ((size_t)b * S_ + rowA + 8) * D_ + col;
        uint32_t ph, pl;
        packsplit(acc[nt][0] * inv0, acc[nt][1] * inv0, ph, pl);
        *(uint32_t*)(z_hi + offA) = ph;
        *(uint32_t*)(z_lo + offA) = pl;
        packsplit(acc[nt][2] * inv1, acc[nt][3] * inv1, ph, pl);
        *(uint32_t*)(z_hi + offB) = ph;
        *(uint32_t*)(z_lo + offB) = pl;
    }
}

// ---------------- Host launch ----------------
template <typename Tp>
static Tp* sym_addr(const void* sym) {
    void* p = nullptr;
    cudaGetSymbolAddress(&p, sym);
    return (Tp*)p;
}

extern "C" void kernel_launch(void* const* d_in, const int* in_sizes, int n_in,
                              void* d_out, int out_size) {
    const float* x     = (const float*)d_in[0];
    const float* W_Q   = (const float*)d_in[1];
    const float* W_K   = (const float*)d_in[2];
    const float* W_V   = (const float*)d_in[3];
    const float* W_O   = (const float*)d_in[4];
    const float* b_Q   = (const float*)d_in[5];
    const float* b_K   = (const float*)d_in[6];
    const float* b_V   = (const float*)d_in[7];
    const float* b_O   = (const float*)d_in[8];
    const float* W_in  = (const float*)d_in[9];
    const float* b_in  = (const float*)d_in[10];
    const float* W_out = (const float*)d_in[11];
    const float* b_out = (const float*)d_in[12];
    float* out = (float*)d_out;

    __nv_bfloat16* xn_hi  = sym_addr<__nv_bfloat16>(g_xn_hi);
    __nv_bfloat16* xn_lo  = sym_addr<__nv_bfloat16>(g_xn_lo);
    float*         qkv    = sym_addr<float>(g_qkv);
    __nv_bfloat16* z_hi   = sym_addr<__nv_bfloat16>(g_z_hi);
    __nv_bfloat16* z_lo   = sym_addr<__nv_bfloat16>(g_z_lo);
    float*         rmid   = sym_addr<float>(g_rmid);
    __nv_bfloat16* m_hi   = sym_addr<__nv_bfloat16>(g_m_hi);
    __nv_bfloat16* m_lo   = sym_addr<__nv_bfloat16>(g_m_lo);
    __nv_bfloat16* hid_hi = sym_addr<__nv_bfloat16>(g_hid_hi);
    __nv_bfloat16* hid_lo = sym_addr<__nv_bfloat16>(g_hid_lo);
    __nv_bfloat16* Wqkv_hi = sym_addr<__nv_bfloat16>(g_Wqkv_hi);
    __nv_bfloat16* Wqkv_lo = sym_addr<__nv_bfloat16>(g_Wqkv_lo);
    __nv_bfloat16* Wo_hi   = sym_addr<__nv_bfloat16>(g_Wo_hi);
    __nv_bfloat16* Wo_lo   = sym_addr<__nv_bfloat16>(g_Wo_lo);
    __nv_bfloat16* Win_hi  = sym_addr<__nv_bfloat16>(g_Win_hi);
    __nv_bfloat16* Win_lo  = sym_addr<__nv_bfloat16>(g_Win_lo);
    __nv_bfloat16* Wout_hi = sym_addr<__nv_bfloat16>(g_Wout_hi);
    __nv_bfloat16* Wout_lo = sym_addr<__nv_bfloat16>(g_Wout_lo);
    float*         bqkv    = sym_addr<float>(g_bqkv);

    cudaFuncSetAttribute(gemm_mma<0,0,0>, cudaFuncAttributeMaxDynamicSharedMemorySize, GEMM_SMEM);
    cudaFuncSetAttribute(gemm_mma<0,1,0>, cudaFuncAttributeMaxDynamicSharedMemorySize, GEMM_SMEM);
    cudaFuncSetAttribute(gemm_mma<1,0,1>, cudaFuncAttributeMaxDynamicSharedMemorySize, GEMM_SMEM);

    // Fused weight splits + bias concat (1 launch) + W_O gather (1 launch)
    const int total4 = N4_ALL + 3072;
    split_all_kernel<<<(total4 + 255) / 256, 256>>>(
        W_Q, W_K, W_V, W_in, W_out,
        Wqkv_hi, Wqkv_lo, Win_hi, Win_lo, Wout_hi, Wout_lo,
        b_Q, b_K, b_V, bqkv);
    wo_split_kernel<<<(D_ * D_) / 256, 256>>>(W_O, Wo_hi, Wo_lo);

    // LN1 -> xn hi/lo
    ln_split_kernel<<<T_, 256>>>(x, xn_hi, xn_lo);

    // Fused QKV projection: qkv[T,3072]
    gemm_mma<0,0,0><<<dim3(3072 / 128, T_ / 128), 256, GEMM_SMEM>>>(
        T_, 3072, D_, xn_hi, xn_lo, Wqkv_hi, Wqkv_lo, bqkv, nullptr, qkv, nullptr, nullptr);

    // Tensor-core attention -> z hi/lo
    attn_mma_kernel<<<dim3(S_ / 64, B_ * H_), 128>>>(qkv, z_hi, z_lo);

    // O projection + residual: rmid = x + z @ Wo^T + b_O
    gemm_mma<0,1,0><<<dim3(D_ / 128, T_ / 128), 256, GEMM_SMEM>>>(
        T_, D_, D_, z_hi, z_lo, Wo_hi, Wo_lo, b_O, x, rmid, nullptr, nullptr);

    // LN2 -> m hi/lo
    ln_split_kernel<<<T_, 256>>>(rmid, m_hi, m_lo);

    // MLP in + gelu -> hid hi/lo (bf16 split output)
    gemm_mma<1,0,1><<<dim3(DM_ / 128, T_ / 128), 256, GEMM_SMEM>>>(
        T_, DM_, D_, m_hi, m_lo, Win_hi, Win_lo, b_in, nullptr, nullptr, hid_hi, hid_lo);

    // MLP out + residual -> final output
    gemm_mma<0,1,0><<<dim3(D_ / 128, T_ / 128), 256, GEMM_SMEM>>>(
        T_, D_, DM_, hid_hi, hid_lo, Wout_hi, Wout_lo, b_out, rmid, out, nullptr, nullptr);
}

// round 17
// speedup vs baseline: 2.4515x; 1.2535x over previous
#include <cuda_runtime.h>
#include <cuda_bf16.h>
#include <math.h>
#include <stdint.h>

// ---------------- Problem dims ----------------
#define B_      2
#define S_      2048
#define T_      4096          // B*S tokens
#define D_      1024
#define H_      16
#define DH_     64
#define DM_     4096
#define EPSV    1e-5f
#define IGNOREV -100000.0f

// ---------------- Small helpers ----------------
__device__ __forceinline__ uint32_t smem_u32(const void* p) {
    uint32_t a;
    asm("{ .reg .u64 t; cvta.to.shared.u64 t, %1; cvt.u32.u64 %0, t; }" : "=r"(a) : "l"(p));
    return a;
}
__device__ __forceinline__ void split2(float v, __nv_bfloat16& h, __nv_bfloat16& l) {
    h = __float2bfloat16(v);
    l = __float2bfloat16(v - __bfloat162float(h));
}
__device__ __forceinline__ float gelu_new_f(float x) {
    float x3 = x * x * x;
    return 0.5f * x * (1.0f + tanhf(0.7978845608028654f * (x + 0.044715f * x3)));
}

// ---------------- Baseline-PTX tensor-core primitives (sm_80+; valid on sm_103) ----
__device__ __forceinline__ void cp16(uint32_t saddr, const void* g) {
    asm volatile("cp.async.cg.shared.global [%0], [%1], 16;" :: "r"(saddr), "l"(g));
}
__device__ __forceinline__ void cp_commit() {
    asm volatile("cp.async.commit_group;" ::: "memory");
}
template <int N>
__device__ __forceinline__ void cp_wait() {
    asm volatile("cp.async.wait_group %0;" :: "n"(N) : "memory");
}
__device__ __forceinline__ void ldsm4(uint32_t (&r)[4], uint32_t a) {
    asm volatile("ldmatrix.sync.aligned.m8n8.x4.shared.b16 {%0,%1,%2,%3}, [%4];"
                 : "=r"(r[0]), "=r"(r[1]), "=r"(r[2]), "=r"(r[3]) : "r"(a));
}
__device__ __forceinline__ void ldsm4t(uint32_t (&r)[4], uint32_t a) {
    asm volatile("ldmatrix.sync.aligned.m8n8.x4.trans.shared.b16 {%0,%1,%2,%3}, [%4];"
                 : "=r"(r[0]), "=r"(r[1]), "=r"(r[2]), "=r"(r[3]) : "r"(a));
}
__device__ __forceinline__ void mma16816(float (&c)[4], const uint32_t (&a)[4],
                                         uint32_t b0, uint32_t b1) {
    asm volatile(
        "mma.sync.aligned.m16n8k16.row.col.f32.bf16.bf16.f32 "
        "{%0,%1,%2,%3}, {%4,%5,%6,%7}, {%8,%9}, {%0,%1,%2,%3};"
        : "+f"(c[0]), "+f"(c[1]), "+f"(c[2]), "+f"(c[3])
        : "r"(a[0]), "r"(a[1]), "r"(a[2]), "r"(a[3]), "r"(b0), "r"(b1));
}

// ---------------- Scratch (static device globals; no allocation) ----------------
__device__ __nv_bfloat16 g_xn_hi [T_ * D_];
__device__ __nv_bfloat16 g_xn_lo [T_ * D_];
__device__ float         g_qkv   [(size_t)T_ * 3072];
__device__ __nv_bfloat16 g_z_hi  [T_ * D_];
__device__ __nv_bfloat16 g_z_lo  [T_ * D_];
__device__ float         g_rmid  [T_ * D_];
__device__ __nv_bfloat16 g_m_hi  [T_ * D_];
__device__ __nv_bfloat16 g_m_lo  [T_ * D_];
__device__ __nv_bfloat16 g_hid_hi[(size_t)T_ * DM_];
__device__ __nv_bfloat16 g_hid_lo[(size_t)T_ * DM_];
__device__ __nv_bfloat16 g_Wqkv_hi[3 * D_ * D_];
__device__ __nv_bfloat16 g_Wqkv_lo[3 * D_ * D_];
__device__ __nv_bfloat16 g_Wo_hi [D_ * D_];
__device__ __nv_bfloat16 g_Wo_lo [D_ * D_];
__device__ __nv_bfloat16 g_Win_hi[(size_t)DM_ * D_];
__device__ __nv_bfloat16 g_Win_lo[(size_t)DM_ * D_];
__device__ __nv_bfloat16 g_Wout_hi[(size_t)D_ * DM_];
__device__ __nv_bfloat16 g_Wout_lo[(size_t)D_ * DM_];
__device__ float         g_bqkv  [3072];

// ---------------- Fused weight split (all straight [N,K] weights + bias concat) ----
__device__ __forceinline__ void split4_store(float4 v,
                                             __nv_bfloat16* __restrict__ hi,
                                             __nv_bfloat16* __restrict__ lo, int i) {
    __nv_bfloat16 h0,h1,h2,h3,l0,l1,l2,l3;
    split2(v.x,h0,l0); split2(v.y,h1,l1); split2(v.z,h2,l2); split2(v.w,h3,l3);
    uint32_t ph0 = (uint32_t)__bfloat16_as_ushort(h0) | ((uint32_t)__bfloat16_as_ushort(h1) << 16);
    uint32_t ph1 = (uint32_t)__bfloat16_as_ushort(h2) | ((uint32_t)__bfloat16_as_ushort(h3) << 16);
    uint32_t pl0 = (uint32_t)__bfloat16_as_ushort(l0) | ((uint32_t)__bfloat16_as_ushort(l1) << 16);
    uint32_t pl1 = (uint32_t)__bfloat16_as_ushort(l2) | ((uint32_t)__bfloat16_as_ushort(l3) << 16);
    ((uint2*)hi)[i] = make_uint2(ph0, ph1);
    ((uint2*)lo)[i] = make_uint2(pl0, pl1);
}

#define N4_QKV1 (D_ * D_ / 4)
#define N4_MLP  (DM_ * D_ / 4)
#define N4_ALL  (3 * N4_QKV1 + 2 * N4_MLP)

__global__ void split_all_kernel(const float* __restrict__ WQ, const float* __restrict__ WK,
                                 const float* __restrict__ WV, const float* __restrict__ Win,
                                 const float* __restrict__ Wout,
                                 __nv_bfloat16* __restrict__ Wqkv_hi, __nv_bfloat16* __restrict__ Wqkv_lo,
                                 __nv_bfloat16* __restrict__ Win_hi,  __nv_bfloat16* __restrict__ Win_lo,
                                 __nv_bfloat16* __restrict__ Wout_hi, __nv_bfloat16* __restrict__ Wout_lo,
                                 const float* __restrict__ bq, const float* __restrict__ bk,
                                 const float* __restrict__ bv, float* __restrict__ bqkv) {
    int i = blockIdx.x * 256 + threadIdx.x;
    if (i < N4_ALL) {
        if (i < 3 * N4_QKV1) {
            int seg = i / N4_QKV1, j = i - seg * N4_QKV1;
            const float* src = (seg == 0) ? WQ : (seg == 1) ? WK : WV;
            split4_store(((const float4*)src)[j],
                         Wqkv_hi + (size_t)seg * D_ * D_, Wqkv_lo + (size_t)seg * D_ * D_, j);
        } else if (i < 3 * N4_QKV1 + N4_MLP) {
            int j = i - 3 * N4_QKV1;
            split4_store(((const float4*)Win)[j], Win_hi, Win_lo, j);
        } else {
            int j = i - 3 * N4_QKV1 - N4_MLP;
            split4_store(((const float4*)Wout)[j], Wout_hi, Wout_lo, j);
        }
    } else {
        int j = i - N4_ALL;
        if (j < 3072) {
            float v = (j < 1024) ? bq[j] : (j < 2048) ? bk[j - 1024] : bv[j - 2048];
            bqkv[j] = v;
        }
    }
}

// W_O [H, D, DH] -> [N=d][K=h*64+dh] bf16 hi/lo (gather pattern)
__global__ void wo_split_kernel(const float* __restrict__ wo,
                                __nv_bfloat16* __restrict__ hi,
                                __nv_bfloat16* __restrict__ lo) {
    int idx = blockIdx.x * 256 + threadIdx.x;
    int d  = idx >> 10;
    int kk = idx & 1023;
    int h  = kk >> 6, dh = kk & 63;
    float v = wo[(size_t)h * D_ * DH_ + (size_t)d * DH_ + dh];
    __nv_bfloat16 hh, ll; split2(v, hh, ll);
    hi[idx] = hh; lo[idx] = ll;
}

// ---------------- LayerNorm -> bf16 hi/lo ----------------
__global__ void ln_split_kernel(const float* __restrict__ src,
                                __nv_bfloat16* __restrict__ hi,
                                __nv_bfloat16* __restrict__ lo) {
    int row = blockIdx.x;
    float4 vv = ((const float4*)(src + (size_t)row * D_))[threadIdx.x];
    float s  = vv.x + vv.y + vv.z + vv.w;
    float s2 = vv.x*vv.x + vv.y*vv.y + vv.z*vv.z + vv.w*vv.w;
    #pragma unroll
    for (int o = 16; o > 0; o >>= 1) {
        s  += __shfl_xor_sync(0xffffffffu, s,  o);
        s2 += __shfl_xor_sync(0xffffffffu, s2, o);
    }
    __shared__ float ws[8], ws2[8];
    __shared__ float s_mean, s_r;
    int w = threadIdx.x >> 5;
    if ((threadIdx.x & 31) == 0) { ws[w] = s; ws2[w] = s2; }
    __syncthreads();
    if (threadIdx.x == 0) {
        float a = 0.f, b2 = 0.f;
        #pragma unroll
        for (int i = 0; i < 8; i++) { a += ws[i]; b2 += ws2[i]; }
        float mean = a * (1.f / D_);
        float var  = b2 * (1.f / D_) - mean * mean;
        s_mean = mean; s_r = rsqrtf(var + EPSV);
    }
    __syncthreads();
    float mean = s_mean, r = s_r;
    float o0 = (vv.x - mean) * r, o1 = (vv.y - mean) * r;
    float o2 = (vv.z - mean) * r, o3 = (vv.w - mean) * r;
    __nv_bfloat16 h0,h1,h2,h3,l0,l1,l2,l3;
    split2(o0,h0,l0); split2(o1,h1,l1); split2(o2,h2,l2); split2(o3,h3,l3);
    uint32_t ph0 = (uint32_t)__bfloat16_as_ushort(h0) | ((uint32_t)__bfloat16_as_ushort(h1) << 16);
    uint32_t ph1 = (uint32_t)__bfloat16_as_ushort(h2) | ((uint32_t)__bfloat16_as_ushort(h3) << 16);
    uint32_t pl0 = (uint32_t)__bfloat16_as_ushort(l0) | ((uint32_t)__bfloat16_as_ushort(l1) << 16);
    uint32_t pl1 = (uint32_t)__bfloat16_as_ushort(l2) | ((uint32_t)__bfloat16_as_ushort(l3) << 16);
    size_t base = (size_t)row * D_ + threadIdx.x * 4;
    ((uint2*)(hi + base))[0] = make_uint2(ph0, ph1);
    ((uint2*)(lo + base))[0] = make_uint2(pl0, pl1);
}

// ========== mma.sync bf16-split GEMM — CTA 256x128, warp tile 64x64, 1 CTA/SM =====
#define GSM_STRIDE 40
#define GSM_AROW   256                         // A rows per CTA tile
#define GSM_BROW   128                         // B rows per CTA tile
#define GSM_A_B    (GSM_AROW * GSM_STRIDE * 2) // 20480 B per A array
#define GSM_B_B    (GSM_BROW * GSM_STRIDE * 2) // 10240 B per B array
#define OFF_AHI    0
#define OFF_ALO    (GSM_A_B)
#define OFF_BHI    (2 * GSM_A_B)
#define OFF_BLO    (2 * GSM_A_B + GSM_B_B)
#define GSM_STAGE_B (2 * GSM_A_B + 2 * GSM_B_B)  // 61440 B per stage
#define GEMM_SMEM  (2 * GSM_STAGE_B)             // 122880 B

__device__ __forceinline__ void fill_stage(
    uint32_t sbase,
    const __nv_bfloat16* __restrict__ Ahi, const __nv_bfloat16* __restrict__ Alo,
    const __nv_bfloat16* __restrict__ Bhi, const __nv_bfloat16* __restrict__ Blo,
    int m0, int n0, int kb, int K, int tid) {
    // A: 256 rows x 4 chunks of 8 bf16 = 1024 chunks (hi & lo together)
    #pragma unroll
    for (int it = 0; it < 4; ++it) {
        int ch = tid + it * 256;
        int row = ch >> 2, kc = ch & 3;
        uint32_t soff = (uint32_t)(row * GSM_STRIDE + kc * 8) * 2;
        size_t ga = (size_t)(m0 + row) * K + kb + kc * 8;
        cp16(sbase + OFF_AHI + soff, Ahi + ga);
        cp16(sbase + OFF_ALO + soff, Alo + ga);
    }
    // B: 128 rows x 4 chunks = 512 chunks
    #pragma unroll
    for (int it = 0; it < 2; ++it) {
        int ch = tid + it * 256;
        int row = ch >> 2, kc = ch & 3;
        uint32_t soff = (uint32_t)(row * GSM_STRIDE + kc * 8) * 2;
        size_t gb = (size_t)(n0 + row) * K + kb + kc * 8;
        cp16(sbase + OFF_BHI + soff, Bhi + gb);
        cp16(sbase + OFF_BLO + soff, Blo + gb);
    }
}

template <int ACT, int RES, int OUTBF16>
__global__ void __launch_bounds__(256, 1)
gemm_mma(int M, int N, int K,
         const __nv_bfloat16* __restrict__ Ahi, const __nv_bfloat16* __restrict__ Alo,
         const __nv_bfloat16* __restrict__ Bhi, const __nv_bfloat16* __restrict__ Blo,
         const float* __restrict__ bias, const float* __restrict__ resid,
         float* __restrict__ Cf,
         __nv_bfloat16* __restrict__ Chi, __nv_bfloat16* __restrict__ Clo) {
    extern __shared__ char sm_raw[];
    uint32_t sb = smem_u32(sm_raw);
    const int tid  = threadIdx.x;
    const int wid  = tid >> 5;
    const int lane = tid & 31;
    const int m0 = blockIdx.y * 256;
    const int n0 = blockIdx.x * 128;
    const int wr0 = (wid >> 1) * 64;      // 4 row-groups of 64
    const int wc0 = (wid & 1) * 64;       // 2 col-groups of 64

    float acc[4][8][4];                   // 128 accumulator regs
    #pragma unroll
    for (int mt = 0; mt < 4; ++mt)
        #pragma unroll
        for (int j = 0; j < 8; ++j)
            #pragma unroll
            for (int q = 0; q < 4; ++q) acc[mt][j][q] = 0.f;

    const int nst = K >> 5;

    fill_stage(sb, Ahi, Alo, Bhi, Blo, m0, n0, 0, K, tid);
    cp_commit();

    for (int c = 0; c < nst; ++c) {
        if (c + 1 < nst)
            fill_stage(sb + (uint32_t)((c + 1) & 1) * GSM_STAGE_B,
                       Ahi, Alo, Bhi, Blo, m0, n0, (c + 1) << 5, K, tid);
        cp_commit();
        cp_wait<1>();
        __syncthreads();

        uint32_t st = sb + (uint32_t)(c & 1) * GSM_STAGE_B;
        #pragma unroll
        for (int ks = 0; ks < 2; ++ks) {
            const int k0 = ks * 16;
            uint32_t Ah[4][4], Al[4][4];
            #pragma unroll
            for (int mt = 0; mt < 4; ++mt) {
                int arow = wr0 + mt * 16 + (lane & 15);
                uint32_t aoff = (uint32_t)(arow * GSM_STRIDE + k0 + ((lane >> 4) << 3)) * 2;
                ldsm4(Ah[mt], st + OFF_AHI + aoff);
                ldsm4(Al[mt], st + OFF_ALO + aoff);
            }
            #pragma unroll
            for (int np = 0; np < 4; ++np) {
                int quad = lane >> 3;
                int brow = wc0 + np * 16 + ((quad >> 1) << 3) + (lane & 7);
                uint32_t boff = (uint32_t)(brow * GSM_STRIDE + k0 + ((quad & 1) << 3)) * 2;
                uint32_t Bh[4], Bl[4];
                ldsm4(Bh, st + OFF_BHI + boff);
                ldsm4(Bl, st + OFF_BLO + boff);
                #pragma unroll
                for (int mt = 0; mt < 4; ++mt) {
                    mma16816(acc[mt][2*np],   Ah[mt], Bh[0], Bh[1]);
                    mma16816(acc[mt][2*np],   Ah[mt], Bl[0], Bl[1]);
                    mma16816(acc[mt][2*np],   Al[mt], Bh[0], Bh[1]);
                    mma16816(acc[mt][2*np+1], Ah[mt], Bh[2], Bh[3]);
                    mma16816(acc[mt][2*np+1], Ah[mt], Bl[2], Bl[3]);
                    mma16816(acc[mt][2*np+1], Al[mt], Bh[2], Bh[3]);
                }
            }
        }
        __syncthreads();
    }

    const int qrow = lane >> 2;
    const int qcol = (lane & 3) * 2;
    #pragma unroll
    for (int mt = 0; mt < 4; ++mt)
        #pragma unroll
        for (int j = 0; j < 8; ++j)
            #pragma unroll
            for (int half = 0; half < 2; ++half) {
                int row = m0 + wr0 + mt * 16 + qrow + half * 8;
                int col = n0 + wc0 + j * 8 + qcol;
                float v0 = acc[mt][j][half * 2 + 0] + bias[col];
                float v1 = acc[mt][j][half * 2 + 1] + bias[col + 1];
                if (ACT) { v0 = gelu_new_f(v0); v1 = gelu_new_f(v1); }
                size_t off = (size_t)row * N + col;
                if (RES) {
                    float2 rr = *(const float2*)(resid + off);
                    v0 += rr.x; v1 += rr.y;
                }
                if (!OUTBF16) {
                    *(float2*)(Cf + off) = make_float2(v0, v1);
                } else {
                    __nv_bfloat16 h0, h1, l0, l1;
                    split2(v0, h0, l0);
                    split2(v1, h1, l1);
                    uint32_t ph = (uint32_t)__bfloat16_as_ushort(h0) |
                                  ((uint32_t)__bfloat16_as_ushort(h1) << 16);
                    uint32_t pl = (uint32_t)__bfloat16_as_ushort(l0) |
                                  ((uint32_t)__bfloat16_as_ushort(l1) << 16);
                    *(uint32_t*)(Chi + off) = ph;
                    *(uint32_t*)(Clo + off) = pl;
                }
            }
}

// ================= Tensor-core causal flash attention (unchanged, verified) =======
#define AT_STRIDE 72

__device__ __forceinline__ void at_fill64(const float* __restrict__ src,
                                          __nv_bfloat16* __restrict__ hi,
                                          __nv_bfloat16* __restrict__ lo,
                                          int tid, float scale) {
    int row = tid >> 1;
    int c0  = (tid & 1) * 32;
    const float4* s4 = (const float4*)(src + (size_t)row * 3072 + c0);
    #pragma unroll
    for (int i = 0; i < 8; ++i) {
        float4 v = s4[i];
        __nv_bfloat16 h0,h1,h2,h3,l0,l1,l2,l3;
        split2(v.x * scale, h0, l0); split2(v.y * scale, h1, l1);
        split2(v.z * scale, h2, l2); split2(v.w * scale, h3, l3);
        uint32_t ph0 = (uint32_t)__bfloat16_as_ushort(h0) | ((uint32_t)__bfloat16_as_ushort(h1) << 16);
        uint32_t ph1 = (uint32_t)__bfloat16_as_ushort(h2) | ((uint32_t)__bfloat16_as_ushort(h3) << 16);
        uint32_t pl0 = (uint32_t)__bfloat16_as_ushort(l0) | ((uint32_t)__bfloat16_as_ushort(l1) << 16);
        uint32_t pl1 = (uint32_t)__bfloat16_as_ushort(l2) | ((uint32_t)__bfloat16_as_ushort(l3) << 16);
        int off = row * AT_STRIDE + c0 + i * 4;
        *(uint2*)(hi + off) = make_uint2(ph0, ph1);
        *(uint2*)(lo + off) = make_uint2(pl0, pl1);
    }
}

__device__ __forceinline__ void packsplit(float f0, float f1, uint32_t& ph, uint32_t& pl) {
    __nv_bfloat16 h0, l0, h1, l1;
    split2(f0, h0, l0); split2(f1, h1, l1);
    ph = (uint32_t)__bfloat16_as_ushort(h0) | ((uint32_t)__bfloat16_as_ushort(h1) << 16);
    pl = (uint32_t)__bfloat16_as_ushort(l0) | ((uint32_t)__bfloat16_as_ushort(l1) << 16);
}

__global__ void __launch_bounds__(128)
attn_mma_kernel(const float* __restrict__ qkv,
                __nv_bfloat16* __restrict__ z_hi, __nv_bfloat16* __restrict__ z_lo) {
    __shared__ __nv_bfloat16 sKh[64 * AT_STRIDE], sKl[64 * AT_STRIDE];
    __shared__ __nv_bfloat16 sVh[64 * AT_STRIDE], sVl[64 * AT_STRIDE];

    const int tid  = threadIdx.x;
    const int wid  = tid >> 5;
    const int lane = tid & 31;
    const int qt = (int)gridDim.x - 1 - (int)blockIdx.x;
    const int bh = blockIdx.y;
    const int b = bh >> 4, h = bh & 15;

    const float* qp = qkv + (size_t)b * S_ * 3072 + h * 64;
    const float* kp = qp + 1024;
    const float* vp = qp + 2048;

    uint32_t aKh = smem_u32(sKh), aKl = smem_u32(sKl);
    uint32_t aVh = smem_u32(sVh), aVl = smem_u32(sVl);

    at_fill64(qp + (size_t)(qt * 64) * 3072, sKh, sKl, tid, 0.125f);
    __syncthreads();
    uint32_t Qh[4][4], Ql[4][4];
    {
        int arow = wid * 16 + (lane & 15);
        #pragma unroll
        for (int ks = 0; ks < 4; ++ks) {
            uint32_t off = (uint32_t)(arow * AT_STRIDE + ks * 16 + ((lane >> 4) << 3)) * 2;
            ldsm4(Qh[ks], aKh + off);
            ldsm4(Ql[ks], aKl + off);
        }
    }
    __syncthreads();

    float m0 = -1e30f, m1 = -1e30f, l0 = 0.f, l1 = 0.f;
    float acc[8][4];
    #pragma unroll
    for (int nt = 0; nt < 8; ++nt)
        #pragma unroll
        for (int q = 0; q < 4; ++q) acc[nt][q] = 0.f;

    const int myrow = wid * 16 + (lane >> 2);
    const int mycol = (lane & 3) * 2;

    for (int jt = 0; jt <= qt; ++jt) {
        at_fill64(kp + (size_t)(jt * 64) * 3072, sKh, sKl, tid, 1.0f);
        at_fill64(vp + (size_t)(jt * 64) * 3072, sVh, sVl, tid, 1.0f);
        __syncthreads();

        float s[8][4];
        #pragma unroll
        for (int nt = 0; nt < 8; ++nt)
            #pragma unroll
            for (int q = 0; q < 4; ++q) s[nt][q] = 0.f;

        {
            const int quad = lane >> 3;
            #pragma unroll
            for (int np = 0; np < 4; ++np) {
                int brow = np * 16 + ((quad >> 1) << 3) + (lane & 7);
                #pragma unroll
                for (int ks = 0; ks < 4; ++ks) {
                    uint32_t boff = (uint32_t)(brow * AT_STRIDE + ks * 16 + ((quad & 1) << 3)) * 2;
                    uint32_t Bh[4], Bl[4];
                    ldsm4(Bh, aKh + boff);
                    ldsm4(Bl, aKl + boff);
                    mma16816(s[2*np],   Qh[ks], Bh[0], Bh[1]);
                    mma16816(s[2*np],   Qh[ks], Bl[0], Bl[1]);
                    mma16816(s[2*np],   Ql[ks], Bh[0], Bh[1]);
                    mma16816(s[2*np+1], Qh[ks], Bh[2], Bh[3]);
                    mma16816(s[2*np+1], Qh[ks], Bl[2], Bl[3]);
                    mma16816(s[2*np+1], Ql[ks], Bh[2], Bh[3]);
                }
            }
        }

        if (jt == qt) {
            #pragma unroll
            for (int nt = 0; nt < 8; ++nt) {
                int col0 = nt * 8 + mycol;
                if (col0     > myrow)     s[nt][0] = IGNOREV;
                if (col0 + 1 > myrow)     s[nt][1] = IGNOREV;
                if (col0     > myrow + 8) s[nt][2] = IGNOREV;
                if (col0 + 1 > myrow + 8) s[nt][3] = IGNOREV;
            }
        }

        float mx0 = -1e30f, mx1 = -1e30f;
        #pragma unroll
        for (int nt = 0; nt < 8; ++nt) {
            mx0 = fmaxf(mx0, fmaxf(s[nt][0], s[nt][1]));
            mx1 = fmaxf(mx1, fmaxf(s[nt][2], s[nt][3]));
        }
        #pragma unroll
        for (int o = 1; o < 4; o <<= 1) {
            mx0 = fmaxf(mx0, __shfl_xor_sync(0xffffffffu, mx0, o));
            mx1 = fmaxf(mx1, __shfl_xor_sync(0xffffffffu, mx1, o));
        }
        float nm0 = fmaxf(m0, mx0), nm1 = fmaxf(m1, mx1);
        float al0 = __expf(m0 - nm0), al1 = __expf(m1 - nm1);
        float rs0 = 0.f, rs1 = 0.f;
        #pragma unroll
        for (int nt = 0; nt < 8; ++nt) {
            s[nt][0] = __expf(s[nt][0] - nm0); rs0 += s[nt][0];
            s[nt][1] = __expf(s[nt][1] - nm0); rs0 += s[nt][1];
            s[nt][2] = __expf(s[nt][2] - nm1); rs1 += s[nt][2];
            s[nt][3] = __expf(s[nt][3] - nm1); rs1 += s[nt][3];
        }
        #pragma unroll
        for (int o = 1; o < 4; o <<= 1) {
            rs0 += __shfl_xor_sync(0xffffffffu, rs0, o);
            rs1 += __shfl_xor_sync(0xffffffffu, rs1, o);
        }
        l0 = l0 * al0 + rs0; l1 = l1 * al1 + rs1;
        m0 = nm0; m1 = nm1;
        #pragma unroll
        for (int nt = 0; nt < 8; ++nt) {
            acc[nt][0] *= al0; acc[nt][1] *= al0;
            acc[nt][2] *= al1; acc[nt][3] *= al1;
        }

        #pragma unroll
        for (int kt = 0; kt < 4; ++kt) {
            uint32_t Ph[4], Pl[4];
            packsplit(s[2*kt][0],   s[2*kt][1],   Ph[0], Pl[0]);
            packsplit(s[2*kt][2],   s[2*kt][3],   Ph[1], Pl[1]);
            packsplit(s[2*kt+1][0], s[2*kt+1][1], Ph[2], Pl[2]);
            packsplit(s[2*kt+1][2], s[2*kt+1][3], Ph[3], Pl[3]);
            int vrow = kt * 16 + (lane & 15);
            #pragma unroll
            for (int nd = 0; nd < 4; ++nd) {
                uint32_t voff = (uint32_t)(vrow * AT_STRIDE + nd * 16 + ((lane >> 4) << 3)) * 2;
                uint32_t Vhf[4], Vlf[4];
                ldsm4t(Vhf, aVh + voff);
                ldsm4t(Vlf, aVl + voff);
                mma16816(acc[2*nd],   Ph, Vhf[0], Vhf[1]);
                mma16816(acc[2*nd],   Ph, Vlf[0], Vlf[1]);
                mma16816(acc[2*nd],   Pl, Vhf[0], Vhf[1]);
                mma16816(acc[2*nd+1], Ph, Vhf[2], Vhf[3]);
                mma16816(acc[2*nd+1], Ph, Vlf[2], Vlf[3]);
                mma16816(acc[2*nd+1], Pl, Vhf[2], Vhf[3]);
            }
        }
        __syncthreads();
    }

    float inv0 = 1.f / l0, inv1 = 1.f / l1;
    int rowA = qt * 64 + myrow;
    #pragma unroll
    for (int nt = 0; nt < 8; ++nt) {
        int col = h * 64 + nt * 8 + mycol;
        size_t offA = ((size_t)b * S_ + rowA) * D_ + col;
        size_t offB = ((size_t)b * S_ + rowA + 8) * D_ + col;
        uint32_t ph, pl;
        packsplit(acc[nt][0] * inv0, acc[nt][1] * inv0, ph, pl);
        *(uint32_t*)(z_hi + offA) = ph;
        *(uint32_t*)(z_lo + offA) = pl;
        packsplit(acc[nt][2] * inv1, acc[nt][3] * inv1, ph, pl);
        *(uint32_t*)(z_hi + offB) = ph;
        *(uint32_t*)(z_lo + offB) = pl;
    }
}

// ---------------- Host launch ----------------
template <typename Tp>
static Tp* sym_addr(const void* sym) {
    void* p = nullptr;
    cudaGetSymbolAddress(&p, sym);
    return (Tp*)p;
}

extern "C" void kernel_launch(void* const* d_in, const int* in_sizes, int n_in,
                              void* d_out, int out_size) {
    const float* x     = (const float*)d_in[0];
    const float* W_Q   = (const float*)d_in[1];
    const float* W_K   = (const float*)d_in[2];
    const float* W_V   = (const float*)d_in[3];
    const float* W_O   = (const float*)d_in[4];
    const float* b_Q   = (const float*)d_in[5];
    const float* b_K   = (const float*)d_in[6];
    const float* b_V   = (const float*)d_in[7];
    const float* b_O   = (const float*)d_in[8];
    const float* W_in  = (const float*)d_in[9];
    const float* b_in  = (const float*)d_in[10];
    const float* W_out = (const float*)d_in[11];
    const float* b_out = (const float*)d_in[12];
    float* out = (float*)d_out;

    __nv_bfloat16* xn_hi  = sym_addr<__nv_bfloat16>(g_xn_hi);
    __nv_bfloat16* xn_lo  = sym_addr<__nv_bfloat16>(g_xn_lo);
    float*         qkv    = sym_addr<float>(g_qkv);
    __nv_bfloat16* z_hi   = sym_addr<__nv_bfloat16>(g_z_hi);
    __nv_bfloat16* z_lo   = sym_addr<__nv_bfloat16>(g_z_lo);
    float*         rmid   = sym_addr<float>(g_rmid);
    __nv_bfloat16* m_hi   = sym_addr<__nv_bfloat16>(g_m_hi);
    __nv_bfloat16* m_lo   = sym_addr<__nv_bfloat16>(g_m_lo);
    __nv_bfloat16* hid_hi = sym_addr<__nv_bfloat16>(g_hid_hi);
    __nv_bfloat16* hid_lo = sym_addr<__nv_bfloat16>(g_hid_lo);
    __nv_bfloat16* Wqkv_hi = sym_addr<__nv_bfloat16>(g_Wqkv_hi);
    __nv_bfloat16* Wqkv_lo = sym_addr<__nv_bfloat16>(g_Wqkv_lo);
    __nv_bfloat16* Wo_hi   = sym_addr<__nv_bfloat16>(g_Wo_hi);
    __nv_bfloat16* Wo_lo   = sym_addr<__nv_bfloat16>(g_Wo_lo);
    __nv_bfloat16* Win_hi  = sym_addr<__nv_bfloat16>(g_Win_hi);
    __nv_bfloat16* Win_lo  = sym_addr<__nv_bfloat16>(g_Win_lo);
    __nv_bfloat16* Wout_hi = sym_addr<__nv_bfloat16>(g_Wout_hi);
    __nv_bfloat16* Wout_lo = sym_addr<__nv_bfloat16>(g_Wout_lo);
    float*         bqkv    = sym_addr<float>(g_bqkv);

    cudaFuncSetAttribute(gemm_mma<0,0,0>, cudaFuncAttributeMaxDynamicSharedMemorySize, GEMM_SMEM);
    cudaFuncSetAttribute(gemm_mma<0,1,0>, cudaFuncAttributeMaxDynamicSharedMemorySize, GEMM_SMEM);
    cudaFuncSetAttribute(gemm_mma<1,0,1>, cudaFuncAttributeMaxDynamicSharedMemorySize, GEMM_SMEM);

    // Fused weight splits + bias concat (1 launch) + W_O gather (1 launch)
    const int total4 = N4_ALL + 3072;
    split_all_kernel<<<(total4 + 255) / 256, 256>>>(
        W_Q, W_K, W_V, W_in, W_out,
        Wqkv_hi, Wqkv_lo, Win_hi, Win_lo, Wout_hi, Wout_lo,
        b_Q, b_K, b_V, bqkv);
    wo_split_kernel<<<(D_ * D_) / 256, 256>>>(W_O, Wo_hi, Wo_lo);

    // LN1 -> xn hi/lo
    ln_split_kernel<<<T_, 256>>>(x, xn_hi, xn_lo);

    // Fused QKV projection: qkv[T,3072]   grid = (N/128, M/256)
    gemm_mma<0,0,0><<<dim3(3072 / 128, T_ / 256), 256, GEMM_SMEM>>>(
        T_, 3072, D_, xn_hi, xn_lo, Wqkv_hi, Wqkv_lo, bqkv, nullptr, qkv, nullptr, nullptr);

    // Tensor-core attention -> z hi/lo
    attn_mma_kernel<<<dim3(S_ / 64, B_ * H_), 128>>>(qkv, z_hi, z_lo);

    // O projection + residual: rmid = x + z @ Wo^T + b_O
    gemm_mma<0,1,0><<<dim3(D_ / 128, T_ / 256), 256, GEMM_SMEM>>>(
        T_, D_, D_, z_hi, z_lo, Wo_hi, Wo_lo, b_O, x, rmid, nullptr, nullptr);

    // LN2 -> m hi/lo
    ln_split_kernel<<<T_, 256>>>(rmid, m_hi, m_lo);

    // MLP in + gelu -> hid hi/lo (bf16 split output)
    gemm_mma<1,0,1><<<dim3(DM_ / 128, T_ / 256), 256, GEMM_SMEM>>>(
        T_, DM_, D_, m_hi, m_lo, Win_hi, Win_lo, b_in, nullptr, nullptr, hid_hi, hid_lo);

    // MLP out + residual -> final output
    gemm_mma<0,1,0><<<dim3(D_ / 128, T_ / 256), 256, GEMM_SMEM>>>(
        T_, D_, DM_, hid_hi, hid_lo, Wout_hi, Wout_lo, b_out, rmid, out, nullptr, nullptr);
}